// round 1
// baseline (speedup 1.0000x reference)
#include <cuda_runtime.h>
#include <math.h>

#ifndef M_PI
#define M_PI 3.14159265358979323846
#endif

#define NN 10000
#define EE 160000
#define FF 128
#define RR 20
#define F3 (3*FF)
#define CUT_D 3.0f

// ---------------- scratch (device globals; no allocation allowed) ----------
__device__ float g_rbfc[EE*RR];     // rbf * cut, per edge
__device__ float g_cut[EE];
__device__ float g_dir[EE*3];
__device__ int   g_inside[EE];
__device__ int   g_deg[NN];
__device__ int   g_rowptr[NN+1];
__device__ int   g_fill[NN];
__device__ int   g_csr[EE];
__device__ float g_sA[NN*FF], g_sB[NN*FF];
__device__ float g_vA[NN*3*FF], g_vB[NN*3*FF];   // stored [N,3,F]
__device__ float g_phi[NN*F3];
__device__ float g_hid[NN*FF];
__device__ float g_Uv[NN*3*FF], g_Vv[NN*3*FF];
__device__ float g_x[NN*2*FF];
__device__ float g_a[NN*F3];

// ---------------- small kernels --------------------------------------------
__global__ void zero_counts_kernel() {
    int i = blockIdx.x * blockDim.x + threadIdx.x;
    if (i < NN) { g_deg[i] = 0; g_fill[i] = 0; }
}

__global__ void edge_pre_kernel(const float* __restrict__ pos,
                                const int* __restrict__ idx_i,
                                const int* __restrict__ idx_j) {
    int e = blockIdx.x * blockDim.x + threadIdx.x;
    if (e >= EE) return;
    int i = idx_i[e], j = idx_j[e];
    float rx = pos[j*3+0] - pos[i*3+0];
    float ry = pos[j*3+1] - pos[i*3+1];
    float rz = pos[j*3+2] - pos[i*3+2];
    float sq = rx*rx + ry*ry + rz*rz;
    float d  = sqrtf(sq);
    float inv = 1.0f / d;
    g_dir[e*3+0] = rx*inv;
    g_dir[e*3+1] = ry*inv;
    g_dir[e*3+2] = rz*inv;
    int ins = (d < CUT_D) ? 1 : 0;
    float cut = ins ? 0.5f * (cosf((float)M_PI * d / CUT_D) + 1.0f) : 0.0f;
    g_cut[e] = cut;
    g_inside[e] = ins;
    float base = (float)M_PI * d / CUT_D;
    float ic = inv * cut;
    #pragma unroll
    for (int k = 0; k < RR; k++) {
        g_rbfc[e*RR+k] = ins ? sinf((float)(k+1) * base) * ic : 0.0f;
    }
    if (ins) atomicAdd(&g_deg[i], 1);
}

// single-block exclusive scan over g_deg -> g_rowptr
__global__ void scan_kernel() {
    __shared__ int sh[1024];
    __shared__ int carry;
    int tid = threadIdx.x;
    if (tid == 0) { carry = 0; g_rowptr[0] = 0; }
    __syncthreads();
    for (int base = 0; base < NN; base += 1024) {
        int i = base + tid;
        int v = (i < NN) ? g_deg[i] : 0;
        sh[tid] = v;
        __syncthreads();
        for (int off = 1; off < 1024; off <<= 1) {
            int add = (tid >= off) ? sh[tid-off] : 0;
            __syncthreads();
            sh[tid] += add;
            __syncthreads();
        }
        if (i < NN) g_rowptr[i+1] = sh[tid] + carry;
        __syncthreads();
        if (tid == 0) carry += sh[1023];
        __syncthreads();
    }
}

__global__ void scatter_kernel(const int* __restrict__ idx_i) {
    int e = blockIdx.x * blockDim.x + threadIdx.x;
    if (e >= EE) return;
    if (!g_inside[e]) return;
    int i = idx_i[e];
    int p = g_rowptr[i] + atomicAdd(&g_fill[i], 1);
    g_csr[p] = e;
}

__global__ void init_kernel(const int* __restrict__ z, const float* __restrict__ emb) {
    int idx = blockIdx.x * blockDim.x + threadIdx.x;
    if (idx >= NN*FF) return;
    int n = idx / FF, f = idx % FF;
    g_sA[idx] = emb[z[n]*FF + f];
    g_vA[n*F3 + f]        = 0.0f;
    g_vA[n*F3 + FF + f]   = 0.0f;
    g_vA[n*F3 + 2*FF + f] = 0.0f;
}

// ---------------- SGEMM: C[M,Nc] = act(A[M,K] @ B[K,Nc] + bias) -------------
// Nc multiple of 64, K multiple of 16. act: 0 = none, 1 = silu.
__global__ __launch_bounds__(256) void sgemm_kernel(
    const float* __restrict__ A, const float* __restrict__ B,
    const float* __restrict__ bias, float* __restrict__ C,
    int M, int Nc, int K, int act)
{
    __shared__ float As[16][65];
    __shared__ float Bs[16][64];
    int tid = threadIdx.x;
    int tcol = tid % 16;            // 16 cols of 4
    int trow = tid / 16;            // 16 rows of 4
    int rowBase = blockIdx.y * 64;
    int colBase = blockIdx.x * 64;
    float acc[4][4] = {};
    for (int k0 = 0; k0 < K; k0 += 16) {
        #pragma unroll
        for (int i = 0; i < 4; i++) {
            int idx = tid + i*256;          // 0..1023
            int r = idx >> 4;               // 0..63
            int c = idx & 15;
            int gr = rowBase + r;
            As[c][r] = (gr < M) ? A[(size_t)gr*K + k0 + c] : 0.0f;
        }
        #pragma unroll
        for (int i = 0; i < 4; i++) {
            int idx = tid + i*256;
            int r = idx >> 6;               // 0..15
            int c = idx & 63;
            Bs[r][c] = B[(size_t)(k0+r)*Nc + colBase + c];
        }
        __syncthreads();
        #pragma unroll
        for (int k = 0; k < 16; k++) {
            float aF[4], bF[4];
            #pragma unroll
            for (int i = 0; i < 4; i++) aF[i] = As[k][trow*4+i];
            #pragma unroll
            for (int j = 0; j < 4; j++) bF[j] = Bs[k][tcol*4+j];
            #pragma unroll
            for (int i = 0; i < 4; i++)
                #pragma unroll
                for (int j = 0; j < 4; j++)
                    acc[i][j] += aF[i] * bF[j];
        }
        __syncthreads();
    }
    #pragma unroll
    for (int i = 0; i < 4; i++) {
        int gr = rowBase + trow*4 + i;
        if (gr >= M) continue;
        #pragma unroll
        for (int j = 0; j < 4; j++) {
            int gc = colBase + tcol*4 + j;
            float v = acc[i][j] + (bias ? bias[gc] : 0.0f);
            if (act == 1) v = v / (1.0f + expf(-v));
            C[(size_t)gr*Nc + gc] = v;
        }
    }
}

// ---------------- fused message kernel --------------------------------------
// thread f in [0,128). per node: gather over incoming CSR edges.
__global__ __launch_bounds__(128) void msg_kernel(
    const float* __restrict__ sIn, const float* __restrict__ vIn,
    const float* __restrict__ phi,
    float* __restrict__ sOut, float* __restrict__ vOut,
    const int* __restrict__ idx_j,
    const float* __restrict__ rbw, const float* __restrict__ rbb)
{
    int f = threadIdx.x;
    float wvv[RR], wss[RR], wvs[RR];
    #pragma unroll
    for (int k = 0; k < RR; k++) {
        wvv[k] = rbw[k*F3 + f];
        wss[k] = rbw[k*F3 + FF + f];
        wvs[k] = rbw[k*F3 + 2*FF + f];
    }
    float bvv = rbb[f], bss = rbb[FF+f], bvs = rbb[2*FF+f];

    for (int i = blockIdx.x; i < NN; i += gridDim.x) {
        int p0 = g_rowptr[i], p1 = g_rowptr[i+1];
        float accs = 0.f, av0 = 0.f, av1 = 0.f, av2 = 0.f;
        for (int p = p0; p < p1; p++) {
            int e = g_csr[p];
            int j = idx_j[e];
            float cut = g_cut[e];
            float d0 = g_dir[e*3+0], d1 = g_dir[e*3+1], d2 = g_dir[e*3+2];
            float Wv = bvv*cut, Ws = bss*cut, Wq = bvs*cut;
            const float* rc = &g_rbfc[e*RR];
            #pragma unroll
            for (int k = 0; k < RR; k++) {
                float r = rc[k];
                Wv += r * wvv[k];
                Ws += r * wss[k];
                Wq += r * wvs[k];
            }
            const float* ph = &phi[(size_t)j * F3];
            float pvv = ph[f]        * Wv;
            float pss = ph[FF + f]   * Ws;
            float pvs = ph[2*FF + f] * Wq;
            accs += pss;
            const float* vj = &vIn[(size_t)j * F3];
            av0 += vj[f]        * pvv + pvs * d0;
            av1 += vj[FF + f]   * pvv + pvs * d1;
            av2 += vj[2*FF + f] * pvv + pvs * d2;
        }
        sOut[(size_t)i*FF + f] = sIn[(size_t)i*FF + f] + accs;
        size_t vb = (size_t)i * F3;
        vOut[vb + f]        = vIn[vb + f]        + av0;
        vOut[vb + FF + f]   = vIn[vb + FF + f]   + av1;
        vOut[vb + 2*FF + f] = vIn[vb + 2*FF + f] + av2;
    }
}

// ---------------- x = concat(safe_norm(Vv), sfeat) --------------------------
__global__ void buildx_kernel(const float* __restrict__ Vv, const float* __restrict__ s) {
    int idx = blockIdx.x * blockDim.x + threadIdx.x;
    if (idx >= NN*2*FF) return;
    int n = idx / (2*FF), c = idx % (2*FF);
    if (c < FF) {
        size_t b = (size_t)n * F3;
        float v0 = Vv[b + c], v1 = Vv[b + FF + c], v2 = Vv[b + 2*FF + c];
        float sq = v0*v0 + v1*v1 + v2*v2;
        g_x[idx] = (sq > 0.0f) ? sqrtf(sq) : 0.0f;
    } else {
        g_x[idx] = s[(size_t)n*FF + (c - FF)];
    }
}

// ---------------- update block ----------------------------------------------
__global__ void update_kernel(float* __restrict__ s, float* __restrict__ v,
                              const float* __restrict__ Uv, const float* __restrict__ Vv) {
    int idx = blockIdx.x * blockDim.x + threadIdx.x;
    if (idx >= NN*FF) return;
    int n = idx / FF, f = idx % FF;
    size_t b = (size_t)n * F3 + f;
    float u0 = Uv[b], u1 = Uv[b + FF], u2 = Uv[b + 2*FF];
    float w0 = Vv[b], w1 = Vv[b + FF], w2 = Vv[b + 2*FF];
    float dot = u0*w0 + u1*w1 + u2*w2;
    const float* an = &g_a[(size_t)n * F3];
    float avv = an[f], asv = an[FF + f], ass = an[2*FF + f];
    v[b]        += u0 * avv;
    v[b + FF]   += u1 * avv;
    v[b + 2*FF] += u2 * avv;
    s[idx] += ass + asv * dot;
}

// ---------------- output: sfeat then vfeat transposed to [N,F,3] ------------
__global__ void output_kernel(const float* __restrict__ s, const float* __restrict__ v,
                              float* __restrict__ out) {
    int idx = blockIdx.x * blockDim.x + threadIdx.x;
    if (idx >= NN*FF) return;
    int n = idx / FF, f = idx % FF;
    out[idx] = s[idx];
    size_t ob = (size_t)NN*FF + (size_t)idx * 3;
    size_t vb = (size_t)n * F3 + f;
    out[ob + 0] = v[vb];
    out[ob + 1] = v[vb + FF];
    out[ob + 2] = v[vb + 2*FF];
}

// ---------------- host orchestration ----------------------------------------
static inline void launch_sgemm(const float* A, const float* B, const float* bias,
                                float* C, int M, int Nc, int K, int act) {
    dim3 grid(Nc / 64, (M + 63) / 64);
    sgemm_kernel<<<grid, 256>>>(A, B, bias, C, M, Nc, K, act);
}

extern "C" void kernel_launch(void* const* d_in, const int* in_sizes, int n_in,
                              void* d_out, int out_size) {
    const int*   z      = (const int*)  d_in[0];
    const float* pos    = (const float*)d_in[1];
    const int*   idx_i  = (const int*)  d_in[2];
    const int*   idx_j  = (const int*)  d_in[3];
    const float* emb    = (const float*)d_in[4];
    const float* msg_w1 = (const float*)d_in[5];
    const float* msg_b1 = (const float*)d_in[6];
    const float* msg_w2 = (const float*)d_in[7];
    const float* msg_b2 = (const float*)d_in[8];
    const float* rbf_w  = (const float*)d_in[9];
    const float* rbf_b  = (const float*)d_in[10];
    const float* upd_U  = (const float*)d_in[11];
    const float* upd_V  = (const float*)d_in[12];
    const float* upd_w1 = (const float*)d_in[13];
    const float* upd_b1 = (const float*)d_in[14];
    const float* upd_w2 = (const float*)d_in[15];
    const float* upd_b2 = (const float*)d_in[16];
    float* out = (float*)d_out;

    float *sA, *sB, *vA, *vB, *phi, *hid, *Uv, *Vv, *aa;
    cudaGetSymbolAddress((void**)&sA,  g_sA);
    cudaGetSymbolAddress((void**)&sB,  g_sB);
    cudaGetSymbolAddress((void**)&vA,  g_vA);
    cudaGetSymbolAddress((void**)&vB,  g_vB);
    cudaGetSymbolAddress((void**)&phi, g_phi);
    cudaGetSymbolAddress((void**)&hid, g_hid);
    cudaGetSymbolAddress((void**)&Uv,  g_Uv);
    cudaGetSymbolAddress((void**)&Vv,  g_Vv);
    cudaGetSymbolAddress((void**)&aa,  g_a);
    float* xx;
    cudaGetSymbolAddress((void**)&xx,  g_x);

    // ---- graph setup (re-done every replay; deterministic) ----
    zero_counts_kernel<<<(NN + 255)/256, 256>>>();
    edge_pre_kernel<<<(EE + 255)/256, 256>>>(pos, idx_i, idx_j);
    scan_kernel<<<1, 1024>>>();
    scatter_kernel<<<(EE + 255)/256, 256>>>(idx_i);
    init_kernel<<<(NN*FF + 255)/256, 256>>>(z, emb);

    float* sCur = sA; float* sNxt = sB;
    float* vCur = vA; float* vNxt = vB;

    for (int l = 0; l < 3; l++) {
        // phi = silu(s @ w1 + b1) @ w2 + b2
        launch_sgemm(sCur, msg_w1 + (size_t)l*FF*FF, msg_b1 + (size_t)l*FF,
                     hid, NN, FF, FF, 1);
        launch_sgemm(hid, msg_w2 + (size_t)l*FF*F3, msg_b2 + (size_t)l*F3,
                     phi, NN, F3, FF, 0);
        // message pass: (sCur, vCur) -> (sNxt, vNxt)
        msg_kernel<<<2000, 128>>>(sCur, vCur, phi, sNxt, vNxt, idx_j,
                                  rbf_w + (size_t)l*RR*F3, rbf_b + (size_t)l*F3);
        // Uv, Vv: [3N,F] @ [F,F]
        launch_sgemm(vNxt, upd_U + (size_t)l*FF*FF, nullptr, Uv, 3*NN, FF, FF, 0);
        launch_sgemm(vNxt, upd_V + (size_t)l*FF*FF, nullptr, Vv, 3*NN, FF, FF, 0);
        // x = concat(||Vv||, s)
        buildx_kernel<<<(NN*2*FF + 255)/256, 256>>>(Vv, sNxt);
        // a = silu(x @ uw1 + ub1) @ uw2 + ub2
        launch_sgemm(xx, upd_w1 + (size_t)l*2*FF*FF, upd_b1 + (size_t)l*FF,
                     hid, NN, FF, 2*FF, 1);
        launch_sgemm(hid, upd_w2 + (size_t)l*FF*F3, upd_b2 + (size_t)l*F3,
                     aa, NN, F3, FF, 0);
        // in-place update of (sNxt, vNxt)
        update_kernel<<<(NN*FF + 255)/256, 256>>>(sNxt, vNxt, Uv, Vv);

        // swap buffers
        float* t;
        t = sCur; sCur = sNxt; sNxt = t;
        t = vCur; vCur = vNxt; vNxt = t;
    }

    output_kernel<<<(NN*FF + 255)/256, 256>>>(sCur, vCur, out);
}

// round 2
// speedup vs baseline: 1.0981x; 1.0981x over previous
#include <cuda_runtime.h>
#include <math.h>

#ifndef M_PI
#define M_PI 3.14159265358979323846
#endif

#define NN 10000
#define EE 160000
#define FF 128
#define RR 20
#define F3 (3*FF)
#define CUT_D 3.0f
#define LL 3

// ---------------- scratch (device globals; no allocation allowed) ----------
__device__ float g_rbfc[EE*RR];     // rbf * cut, per edge
__device__ float g_cut[EE];
__device__ float g_dir[EE*3];
__device__ int   g_inside[EE];
__device__ int   g_deg[NN];
__device__ int   g_rowptr[NN+1];
__device__ int   g_fill[NN];
__device__ int   g_csr[EE];
__device__ float g_sA[NN*FF], g_sB[NN*FF];
__device__ float g_vA[NN*3*FF], g_vB[NN*3*FF];   // stored [N,3,F]
__device__ float g_phi[NN*F3];
__device__ float g_hid[NN*FF];
__device__ float g_UVw[LL*FF*2*FF];              // packed [L][F][2F]: U | V
__device__ float g_UVv[NN*3*2*FF];               // [3N][256]: Uv | Vv
__device__ float g_x[NN*2*FF];
__device__ float g_a[NN*F3];

// ---------------- small kernels --------------------------------------------
__global__ void zero_counts_kernel() {
    int i = blockIdx.x * blockDim.x + threadIdx.x;
    if (i < NN) { g_deg[i] = 0; g_fill[i] = 0; }
}

__global__ void edge_pre_kernel(const float* __restrict__ pos,
                                const int* __restrict__ idx_i,
                                const int* __restrict__ idx_j) {
    int e = blockIdx.x * blockDim.x + threadIdx.x;
    if (e >= EE) return;
    int i = idx_i[e], j = idx_j[e];
    float rx = pos[j*3+0] - pos[i*3+0];
    float ry = pos[j*3+1] - pos[i*3+1];
    float rz = pos[j*3+2] - pos[i*3+2];
    float sq = rx*rx + ry*ry + rz*rz;
    float d  = sqrtf(sq);
    float inv = 1.0f / d;
    g_dir[e*3+0] = rx*inv;
    g_dir[e*3+1] = ry*inv;
    g_dir[e*3+2] = rz*inv;
    int ins = (d < CUT_D) ? 1 : 0;
    float base = (float)M_PI * d / CUT_D;
    float s1, c1;
    sincosf(base, &s1, &c1);
    float cut = ins ? 0.5f * (c1 + 1.0f) : 0.0f;
    g_cut[e] = cut;
    g_inside[e] = ins;
    float ic = inv * cut;          // zero when outside cutoff
    float twoc = 2.0f * c1;
    float sk = s1, skm1 = 0.0f;
    #pragma unroll
    for (int k = 0; k < RR; k++) {
        g_rbfc[e*RR+k] = sk * ic;
        float nxt = twoc * sk - skm1;
        skm1 = sk; sk = nxt;
    }
    if (ins) atomicAdd(&g_deg[i], 1);
}

// single-block exclusive scan over g_deg -> g_rowptr
__global__ void scan_kernel() {
    __shared__ int sh[1024];
    __shared__ int carry;
    int tid = threadIdx.x;
    if (tid == 0) { carry = 0; g_rowptr[0] = 0; }
    __syncthreads();
    for (int base = 0; base < NN; base += 1024) {
        int i = base + tid;
        int v = (i < NN) ? g_deg[i] : 0;
        sh[tid] = v;
        __syncthreads();
        for (int off = 1; off < 1024; off <<= 1) {
            int add = (tid >= off) ? sh[tid-off] : 0;
            __syncthreads();
            sh[tid] += add;
            __syncthreads();
        }
        if (i < NN) g_rowptr[i+1] = sh[tid] + carry;
        __syncthreads();
        if (tid == 0) carry += sh[1023];
        __syncthreads();
    }
}

__global__ void scatter_kernel(const int* __restrict__ idx_i) {
    int e = blockIdx.x * blockDim.x + threadIdx.x;
    if (e >= EE) return;
    if (!g_inside[e]) return;
    int i = idx_i[e];
    int p = g_rowptr[i] + atomicAdd(&g_fill[i], 1);
    g_csr[p] = e;
}

__global__ void init_kernel(const int* __restrict__ z, const float* __restrict__ emb) {
    int idx = blockIdx.x * blockDim.x + threadIdx.x;
    if (idx >= NN*FF) return;
    int n = idx / FF, f = idx % FF;
    g_sA[idx] = emb[z[n]*FF + f];
    g_vA[n*F3 + f]        = 0.0f;
    g_vA[n*F3 + FF + f]   = 0.0f;
    g_vA[n*F3 + 2*FF + f] = 0.0f;
}

// pack all layers' U|V into [L][F][2F]
__global__ void uvpack_kernel(const float* __restrict__ U, const float* __restrict__ V) {
    int idx = blockIdx.x * blockDim.x + threadIdx.x;
    if (idx >= LL*FF*2*FF) return;
    int l = idx / (FF*2*FF);
    int r = idx % (FF*2*FF);
    int f = r / (2*FF), c = r % (2*FF);
    g_UVw[idx] = (c < FF) ? U[(size_t)l*FF*FF + f*FF + c]
                          : V[(size_t)l*FF*FF + f*FF + (c-FF)];
}

// ---------------- SGEMM: C[M,Nc] = act(A[M,K] @ B[K,Nc] + bias) -------------
// Nc multiple of 64, K multiple of 16. act: 0 = none, 1 = silu.
// 128x64 tile, BK=16, 256 threads, 8x4 outputs/thread, float4 everywhere.
#define BM 128
#define BN 64
#define BK 16

__global__ __launch_bounds__(256) void sgemm2_kernel(
    const float* __restrict__ A, const float* __restrict__ B,
    const float* __restrict__ bias, float* __restrict__ C,
    int M, int Nc, int K, int act)
{
    __shared__ float As[BK][BM+4];
    __shared__ float Bs[BK][BN];
    int tid = threadIdx.x;
    int tx = tid & 15;          // N: 4 cols
    int ty = tid >> 4;          // M: 8 rows
    int rowBase = blockIdx.y * BM;
    int colBase = blockIdx.x * BN;

    // A: two float4 per thread. q in {tid, tid+256}; row=q>>2, kquad=(q&3)*4
    int arow0 = tid >> 2;            // 0..63
    int arow1 = arow0 + 64;          // 64..127
    int ak    = (tid & 3) * 4;
    int gr0   = rowBase + arow0;
    int gr1   = rowBase + arow1;
    // B: one float4 per thread: row=tid>>4 (0..15), col=(tid&15)*4
    int brow  = tid >> 4;
    int bcol  = (tid & 15) * 4;

    float acc[8][4];
    #pragma unroll
    for (int i = 0; i < 8; i++)
        #pragma unroll
        for (int j = 0; j < 4; j++) acc[i][j] = 0.0f;

    const float4 zero4 = make_float4(0.f, 0.f, 0.f, 0.f);
    float4 pa0, pa1, pb;

    // prologue: load tile k0=0
    pa0 = (gr0 < M) ? *(const float4*)&A[(size_t)gr0*K + ak] : zero4;
    pa1 = (gr1 < M) ? *(const float4*)&A[(size_t)gr1*K + ak] : zero4;
    pb  = *(const float4*)&B[(size_t)brow*Nc + colBase + bcol];

    for (int k0 = 0; k0 < K; k0 += BK) {
        // store prefetched tile to smem
        As[ak+0][arow0] = pa0.x; As[ak+1][arow0] = pa0.y;
        As[ak+2][arow0] = pa0.z; As[ak+3][arow0] = pa0.w;
        As[ak+0][arow1] = pa1.x; As[ak+1][arow1] = pa1.y;
        As[ak+2][arow1] = pa1.z; As[ak+3][arow1] = pa1.w;
        *(float4*)&Bs[brow][bcol] = pb;
        __syncthreads();

        // prefetch next tile
        bool more = (k0 + BK < K);
        if (more) {
            pa0 = (gr0 < M) ? *(const float4*)&A[(size_t)gr0*K + k0 + BK + ak] : zero4;
            pa1 = (gr1 < M) ? *(const float4*)&A[(size_t)gr1*K + k0 + BK + ak] : zero4;
            pb  = *(const float4*)&B[(size_t)(k0 + BK + brow)*Nc + colBase + bcol];
        }

        #pragma unroll
        for (int k = 0; k < BK; k++) {
            float4 a0 = *(const float4*)&As[k][ty*8];
            float4 a1 = *(const float4*)&As[k][ty*8 + 4];
            float4 b4 = *(const float4*)&Bs[k][tx*4];
            float aF[8] = {a0.x, a0.y, a0.z, a0.w, a1.x, a1.y, a1.z, a1.w};
            float bF[4] = {b4.x, b4.y, b4.z, b4.w};
            #pragma unroll
            for (int i = 0; i < 8; i++)
                #pragma unroll
                for (int j = 0; j < 4; j++)
                    acc[i][j] += aF[i] * bF[j];
        }
        __syncthreads();
    }

    float4 bv = zero4;
    if (bias) bv = *(const float4*)&bias[colBase + tx*4];
    #pragma unroll
    for (int i = 0; i < 8; i++) {
        int gr = rowBase + ty*8 + i;
        if (gr >= M) continue;
        float4 o;
        o.x = acc[i][0] + bv.x;
        o.y = acc[i][1] + bv.y;
        o.z = acc[i][2] + bv.z;
        o.w = acc[i][3] + bv.w;
        if (act == 1) {
            o.x = o.x / (1.0f + expf(-o.x));
            o.y = o.y / (1.0f + expf(-o.y));
            o.z = o.z / (1.0f + expf(-o.z));
            o.w = o.w / (1.0f + expf(-o.w));
        }
        *(float4*)&C[(size_t)gr*Nc + colBase + tx*4] = o;
    }
}

// ---------------- fused message kernel --------------------------------------
__global__ __launch_bounds__(128) void msg_kernel(
    const float* __restrict__ sIn, const float* __restrict__ vIn,
    const float* __restrict__ phi,
    float* __restrict__ sOut, float* __restrict__ vOut,
    const int* __restrict__ idx_j,
    const float* __restrict__ rbw, const float* __restrict__ rbb)
{
    int f = threadIdx.x;
    float wvv[RR], wss[RR], wvs[RR];
    #pragma unroll
    for (int k = 0; k < RR; k++) {
        wvv[k] = rbw[k*F3 + f];
        wss[k] = rbw[k*F3 + FF + f];
        wvs[k] = rbw[k*F3 + 2*FF + f];
    }
    float bvv = rbb[f], bss = rbb[FF+f], bvs = rbb[2*FF+f];

    for (int i = blockIdx.x; i < NN; i += gridDim.x) {
        int p0 = g_rowptr[i], p1 = g_rowptr[i+1];
        float accs = 0.f, av0 = 0.f, av1 = 0.f, av2 = 0.f;
        for (int p = p0; p < p1; p++) {
            int e = g_csr[p];
            int j = idx_j[e];
            float cut = g_cut[e];
            float d0 = g_dir[e*3+0], d1 = g_dir[e*3+1], d2 = g_dir[e*3+2];
            float Wv = bvv*cut, Ws = bss*cut, Wq = bvs*cut;
            const float* rc = &g_rbfc[e*RR];
            #pragma unroll
            for (int k = 0; k < RR; k++) {
                float r = rc[k];
                Wv += r * wvv[k];
                Ws += r * wss[k];
                Wq += r * wvs[k];
            }
            const float* ph = &phi[(size_t)j * F3];
            float pvv = ph[f]        * Wv;
            float pss = ph[FF + f]   * Ws;
            float pvs = ph[2*FF + f] * Wq;
            accs += pss;
            const float* vj = &vIn[(size_t)j * F3];
            av0 += vj[f]        * pvv + pvs * d0;
            av1 += vj[FF + f]   * pvv + pvs * d1;
            av2 += vj[2*FF + f] * pvv + pvs * d2;
        }
        sOut[(size_t)i*FF + f] = sIn[(size_t)i*FF + f] + accs;
        size_t vb = (size_t)i * F3;
        vOut[vb + f]        = vIn[vb + f]        + av0;
        vOut[vb + FF + f]   = vIn[vb + FF + f]   + av1;
        vOut[vb + 2*FF + f] = vIn[vb + 2*FF + f] + av2;
    }
}

// ---------------- x = concat(safe_norm(Vv), sfeat); Vv = g_UVv[:,128:256] ---
__global__ void buildx_kernel(const float* __restrict__ s) {
    int idx = blockIdx.x * blockDim.x + threadIdx.x;
    if (idx >= NN*2*FF) return;
    int n = idx / (2*FF), c = idx % (2*FF);
    if (c < FF) {
        size_t b = (size_t)n * 3 * 256 + 128 + c;
        float v0 = g_UVv[b], v1 = g_UVv[b + 256], v2 = g_UVv[b + 512];
        float sq = v0*v0 + v1*v1 + v2*v2;
        g_x[idx] = (sq > 0.0f) ? sqrtf(sq) : 0.0f;
    } else {
        g_x[idx] = s[(size_t)n*FF + (c - FF)];
    }
}

// ---------------- update block: reads Uv|Vv from g_UVv ----------------------
__global__ void update_kernel(float* __restrict__ s, float* __restrict__ v) {
    int idx = blockIdx.x * blockDim.x + threadIdx.x;
    if (idx >= NN*FF) return;
    int n = idx / FF, f = idx % FF;
    size_t ub = (size_t)n * 3 * 256 + f;      // Uv
    float u0 = g_UVv[ub],       u1 = g_UVv[ub + 256],       u2 = g_UVv[ub + 512];
    float w0 = g_UVv[ub + 128], w1 = g_UVv[ub + 256 + 128], w2 = g_UVv[ub + 512 + 128];
    float dot = u0*w0 + u1*w1 + u2*w2;
    const float* an = &g_a[(size_t)n * F3];
    float avv = an[f], asv = an[FF + f], ass = an[2*FF + f];
    size_t b = (size_t)n * F3 + f;
    v[b]        += u0 * avv;
    v[b + FF]   += u1 * avv;
    v[b + 2*FF] += u2 * avv;
    s[idx] += ass + asv * dot;
}

// ---------------- output: sfeat then vfeat transposed to [N,F,3] ------------
__global__ void output_kernel(const float* __restrict__ s, const float* __restrict__ v,
                              float* __restrict__ out) {
    int idx = blockIdx.x * blockDim.x + threadIdx.x;
    if (idx >= NN*FF) return;
    int n = idx / FF, f = idx % FF;
    out[idx] = s[idx];
    size_t ob = (size_t)NN*FF + (size_t)idx * 3;
    size_t vb = (size_t)n * F3 + f;
    out[ob + 0] = v[vb];
    out[ob + 1] = v[vb + FF];
    out[ob + 2] = v[vb + 2*FF];
}

// ---------------- host orchestration ----------------------------------------
static inline void launch_sgemm(const float* A, const float* B, const float* bias,
                                float* C, int M, int Nc, int K, int act) {
    dim3 grid(Nc / BN, (M + BM - 1) / BM);
    sgemm2_kernel<<<grid, 256>>>(A, B, bias, C, M, Nc, K, act);
}

extern "C" void kernel_launch(void* const* d_in, const int* in_sizes, int n_in,
                              void* d_out, int out_size) {
    const int*   z      = (const int*)  d_in[0];
    const float* pos    = (const float*)d_in[1];
    const int*   idx_i  = (const int*)  d_in[2];
    const int*   idx_j  = (const int*)  d_in[3];
    const float* emb    = (const float*)d_in[4];
    const float* msg_w1 = (const float*)d_in[5];
    const float* msg_b1 = (const float*)d_in[6];
    const float* msg_w2 = (const float*)d_in[7];
    const float* msg_b2 = (const float*)d_in[8];
    const float* rbf_w  = (const float*)d_in[9];
    const float* rbf_b  = (const float*)d_in[10];
    const float* upd_U  = (const float*)d_in[11];
    const float* upd_V  = (const float*)d_in[12];
    const float* upd_w1 = (const float*)d_in[13];
    const float* upd_b1 = (const float*)d_in[14];
    const float* upd_w2 = (const float*)d_in[15];
    const float* upd_b2 = (const float*)d_in[16];
    float* out = (float*)d_out;

    float *sA, *sB, *vA, *vB, *phi, *hid, *UVw, *UVv, *aa, *xx;
    cudaGetSymbolAddress((void**)&sA,  g_sA);
    cudaGetSymbolAddress((void**)&sB,  g_sB);
    cudaGetSymbolAddress((void**)&vA,  g_vA);
    cudaGetSymbolAddress((void**)&vB,  g_vB);
    cudaGetSymbolAddress((void**)&phi, g_phi);
    cudaGetSymbolAddress((void**)&hid, g_hid);
    cudaGetSymbolAddress((void**)&UVw, g_UVw);
    cudaGetSymbolAddress((void**)&UVv, g_UVv);
    cudaGetSymbolAddress((void**)&aa,  g_a);
    cudaGetSymbolAddress((void**)&xx,  g_x);

    // ---- setup (replayed every graph iteration; deterministic) ----
    zero_counts_kernel<<<(NN + 255)/256, 256>>>();
    edge_pre_kernel<<<(EE + 255)/256, 256>>>(pos, idx_i, idx_j);
    scan_kernel<<<1, 1024>>>();
    scatter_kernel<<<(EE + 255)/256, 256>>>(idx_i);
    init_kernel<<<(NN*FF + 255)/256, 256>>>(z, emb);
    uvpack_kernel<<<(LL*FF*2*FF + 255)/256, 256>>>(upd_U, upd_V);

    float* sCur = sA; float* sNxt = sB;
    float* vCur = vA; float* vNxt = vB;

    for (int l = 0; l < 3; l++) {
        // phi = silu(s @ w1 + b1) @ w2 + b2
        launch_sgemm(sCur, msg_w1 + (size_t)l*FF*FF, msg_b1 + (size_t)l*FF,
                     hid, NN, FF, FF, 1);
        launch_sgemm(hid, msg_w2 + (size_t)l*FF*F3, msg_b2 + (size_t)l*F3,
                     phi, NN, F3, FF, 0);
        // message pass: (sCur, vCur) -> (sNxt, vNxt)
        msg_kernel<<<2000, 128>>>(sCur, vCur, phi, sNxt, vNxt, idx_j,
                                  rbf_w + (size_t)l*RR*F3, rbf_b + (size_t)l*F3);
        // [Uv | Vv] = vNxt[3N,F] @ UVw[F,2F]
        launch_sgemm(vNxt, UVw + (size_t)l*FF*2*FF, nullptr, UVv, 3*NN, 2*FF, FF, 0);
        // x = concat(||Vv||, s)
        buildx_kernel<<<(NN*2*FF + 255)/256, 256>>>(sNxt);
        // a = silu(x @ uw1 + ub1) @ uw2 + ub2
        launch_sgemm(xx, upd_w1 + (size_t)l*2*FF*FF, upd_b1 + (size_t)l*FF,
                     hid, NN, FF, 2*FF, 1);
        launch_sgemm(hid, upd_w2 + (size_t)l*FF*F3, upd_b2 + (size_t)l*F3,
                     aa, NN, F3, FF, 0);
        // in-place update of (sNxt, vNxt)
        update_kernel<<<(NN*FF + 255)/256, 256>>>(sNxt, vNxt);

        float* t;
        t = sCur; sCur = sNxt; sNxt = t;
        t = vCur; vCur = vNxt; vNxt = t;
    }

    output_kernel<<<(NN*FF + 255)/256, 256>>>(sCur, vCur, out);
}

// round 4
// speedup vs baseline: 1.1345x; 1.0332x over previous
#include <cuda_runtime.h>
#include <cstdint>
#include <math.h>

#ifndef M_PI
#define M_PI 3.14159265358979323846
#endif

#define NN 10000
#define EE 160000
#define FF 128
#define RR 20
#define F3 (3*FF)
#define CUT_D 3.0f
#define LL 3

// per-layer packed transposed-weight stride (floats)
#define PS 180224
#define OW1 0          /* w1T  [128,128] */
#define OW2 16384      /* w2T  [384,128] */
#define OUV 65536      /* UVwT [256,128] */
#define OU1 98304      /* u1T  [128,256] */
#define OU2 131072     /* u2T  [384,128] */

// ---------------- scratch (device globals; no allocation allowed) ----------
__device__ float g_rbfc[EE*RR];
__device__ float g_cut[EE];
__device__ float g_dir[EE*3];
__device__ int   g_inside[EE];
__device__ int   g_deg[NN];
__device__ int   g_rowptr[NN+1];
__device__ int   g_fill[NN];
__device__ int   g_csr[EE];
__device__ float g_sA[NN*FF], g_sB[NN*FF];
__device__ float g_vA[NN*3*FF], g_vB[NN*3*FF];   // stored [N,3,F]
__device__ float g_phi[NN*F3];
__device__ float g_hid[NN*FF];
__device__ float g_wT[LL*PS];                    // all weights transposed to [N,K]
__device__ float g_UVv[NN*3*2*FF];               // [3N][256]: Uv | Vv
__device__ float g_x[NN*2*FF];
__device__ float g_a[NN*F3];

// ================= tf32 mma.sync GEMM =======================================
// C[M,N] = act(A[M,K] @ BT[N,K]^T + bias). N mult of 64, K mult of 32.
// 3xTF32 hi/lo split for ~fp32 accuracy. Arch-generic PTX (no tcgen05).
#define GBM 128
#define GBN 64
#define GBK 32
#define APAD 36                         /* row stride in floats */
#define SA_HI 0
#define SA_LO (128*APAD)
#define SB_HI (2*128*APAD)
#define SB_LO (2*128*APAD + 64*APAD)
#define SM_FLOATS (2*128*APAD + 2*64*APAD)
#define SM_BYTES  (SM_FLOATS*4)

__device__ __forceinline__ void mma_tf32(float* c, const uint32_t* a, const uint32_t* b) {
    asm volatile(
        "mma.sync.aligned.m16n8k8.row.col.f32.tf32.tf32.f32 "
        "{%0,%1,%2,%3}, {%4,%5,%6,%7}, {%8,%9}, {%0,%1,%2,%3};"
        : "+f"(c[0]), "+f"(c[1]), "+f"(c[2]), "+f"(c[3])
        : "r"(a[0]), "r"(a[1]), "r"(a[2]), "r"(a[3]), "r"(b[0]), "r"(b[1]));
}

__global__ __launch_bounds__(256, 2) void gemm_mma_kernel(
    const float* __restrict__ A, const float* __restrict__ BT,
    const float* __restrict__ bias, float* __restrict__ C,
    int M, int K, int N, int act)
{
    extern __shared__ float sm[];
    int tid  = threadIdx.x;
    int lane = tid & 31;
    int warp = tid >> 5;
    int wm = warp & 3;          // 4 warps along M
    int wn = warp >> 2;         // 2 warps along N
    int g  = lane >> 2;         // 0..7
    int t  = lane & 3;          // 0..3
    int rowBase = blockIdx.y * GBM;
    int colBase = blockIdx.x * GBN;

    float acc[2][4][4];
    #pragma unroll
    for (int mt = 0; mt < 2; mt++)
        #pragma unroll
        for (int nt = 0; nt < 4; nt++)
            #pragma unroll
            for (int q = 0; q < 4; q++) acc[mt][nt][q] = 0.0f;

    const uint32_t MHI = 0xFFFFE000u;

    for (int k0 = 0; k0 < K; k0 += GBK) {
        // ---- A chunk: 128 rows x 32 k -> split hi/lo ----
        #pragma unroll
        for (int it = 0; it < 4; it++) {
            int i = tid + it * 256;
            int row = i >> 3, kq = i & 7;
            int gr = rowBase + row;
            float4 a = make_float4(0.f, 0.f, 0.f, 0.f);
            if (gr < M) a = *(const float4*)&A[(size_t)gr * K + k0 + kq * 4];
            float4 h, l;
            h.x = __uint_as_float(__float_as_uint(a.x) & MHI); l.x = a.x - h.x;
            h.y = __uint_as_float(__float_as_uint(a.y) & MHI); l.y = a.y - h.y;
            h.z = __uint_as_float(__float_as_uint(a.z) & MHI); l.z = a.z - h.z;
            h.w = __uint_as_float(__float_as_uint(a.w) & MHI); l.w = a.w - h.w;
            int off = row * APAD + kq * 4;
            *(float4*)&sm[SA_HI + off] = h;
            *(float4*)&sm[SA_LO + off] = l;
        }
        // ---- B chunk: 64 rows x 32 k ----
        #pragma unroll
        for (int it = 0; it < 2; it++) {
            int i = tid + it * 256;
            int row = i >> 3, kq = i & 7;
            float4 a = *(const float4*)&BT[(size_t)(colBase + row) * K + k0 + kq * 4];
            float4 h, l;
            h.x = __uint_as_float(__float_as_uint(a.x) & MHI); l.x = a.x - h.x;
            h.y = __uint_as_float(__float_as_uint(a.y) & MHI); l.y = a.y - h.y;
            h.z = __uint_as_float(__float_as_uint(a.z) & MHI); l.z = a.z - h.z;
            h.w = __uint_as_float(__float_as_uint(a.w) & MHI); l.w = a.w - h.w;
            int off = row * APAD + kq * 4;
            *(float4*)&sm[SB_HI + off] = h;
            *(float4*)&sm[SB_LO + off] = l;
        }
        __syncthreads();

        #pragma unroll
        for (int ks = 0; ks < 4; ks++) {
            int kk = ks * 8;
            uint32_t aH[2][4], aL[2][4], bH[4][2], bL[4][2];
            #pragma unroll
            for (int mt = 0; mt < 2; mt++) {
                int base = (wm*32 + mt*16 + g) * APAD + kk + t;
                aH[mt][0] = __float_as_uint(sm[SA_HI + base]);
                aH[mt][1] = __float_as_uint(sm[SA_HI + base + 8*APAD]);
                aH[mt][2] = __float_as_uint(sm[SA_HI + base + 4]);
                aH[mt][3] = __float_as_uint(sm[SA_HI + base + 8*APAD + 4]);
                aL[mt][0] = __float_as_uint(sm[SA_LO + base]);
                aL[mt][1] = __float_as_uint(sm[SA_LO + base + 8*APAD]);
                aL[mt][2] = __float_as_uint(sm[SA_LO + base + 4]);
                aL[mt][3] = __float_as_uint(sm[SA_LO + base + 8*APAD + 4]);
            }
            #pragma unroll
            for (int nt = 0; nt < 4; nt++) {
                int base = (wn*32 + nt*8 + g) * APAD + kk + t;
                bH[nt][0] = __float_as_uint(sm[SB_HI + base]);
                bH[nt][1] = __float_as_uint(sm[SB_HI + base + 4]);
                bL[nt][0] = __float_as_uint(sm[SB_LO + base]);
                bL[nt][1] = __float_as_uint(sm[SB_LO + base + 4]);
            }
            #pragma unroll
            for (int mt = 0; mt < 2; mt++)
                #pragma unroll
                for (int nt = 0; nt < 4; nt++) {
                    mma_tf32(acc[mt][nt], aH[mt], bH[nt]);
                    mma_tf32(acc[mt][nt], aH[mt], bL[nt]);
                    mma_tf32(acc[mt][nt], aL[mt], bH[nt]);
                }
        }
        __syncthreads();
    }

    // ---- epilogue: bias + optional silu, float2 stores ----
    #pragma unroll
    for (int mt = 0; mt < 2; mt++) {
        int r0 = rowBase + wm*32 + mt*16 + g;
        int r1 = r0 + 8;
        #pragma unroll
        for (int nt = 0; nt < 4; nt++) {
            int cc = colBase + wn*32 + nt*8 + t*2;
            float b0 = 0.f, b1 = 0.f;
            if (bias) { b0 = bias[cc]; b1 = bias[cc+1]; }
            float o0 = acc[mt][nt][0] + b0;
            float o1 = acc[mt][nt][1] + b1;
            float o2 = acc[mt][nt][2] + b0;
            float o3 = acc[mt][nt][3] + b1;
            if (act == 1) {
                o0 = o0 / (1.0f + expf(-o0));
                o1 = o1 / (1.0f + expf(-o1));
                o2 = o2 / (1.0f + expf(-o2));
                o3 = o3 / (1.0f + expf(-o3));
            }
            if (r0 < M) *(float2*)&C[(size_t)r0*N + cc] = make_float2(o0, o1);
            if (r1 < M) *(float2*)&C[(size_t)r1*N + cc] = make_float2(o2, o3);
        }
    }
}

// ================= graph-structure + elementwise kernels =====================
__global__ void zero_counts_kernel() {
    int i = blockIdx.x * blockDim.x + threadIdx.x;
    if (i < NN) { g_deg[i] = 0; g_fill[i] = 0; }
}

__global__ void edge_pre_kernel(const float* __restrict__ pos,
                                const int* __restrict__ idx_i,
                                const int* __restrict__ idx_j) {
    int e = blockIdx.x * blockDim.x + threadIdx.x;
    if (e >= EE) return;
    int i = idx_i[e], j = idx_j[e];
    float rx = pos[j*3+0] - pos[i*3+0];
    float ry = pos[j*3+1] - pos[i*3+1];
    float rz = pos[j*3+2] - pos[i*3+2];
    float sq = rx*rx + ry*ry + rz*rz;
    float d  = sqrtf(sq);
    float inv = 1.0f / d;
    g_dir[e*3+0] = rx*inv;
    g_dir[e*3+1] = ry*inv;
    g_dir[e*3+2] = rz*inv;
    int ins = (d < CUT_D) ? 1 : 0;
    float base = (float)M_PI * d / CUT_D;
    float s1, c1;
    sincosf(base, &s1, &c1);
    float cut = ins ? 0.5f * (c1 + 1.0f) : 0.0f;
    g_cut[e] = cut;
    g_inside[e] = ins;
    float ic = inv * cut;
    float twoc = 2.0f * c1;
    float sk = s1, skm1 = 0.0f;
    #pragma unroll
    for (int k = 0; k < RR; k++) {
        g_rbfc[e*RR+k] = sk * ic;
        float nxt = twoc * sk - skm1;
        skm1 = sk; sk = nxt;
    }
    if (ins) atomicAdd(&g_deg[i], 1);
}

__global__ void scan_kernel() {
    __shared__ int sh[1024];
    __shared__ int carry;
    int tid = threadIdx.x;
    if (tid == 0) { carry = 0; g_rowptr[0] = 0; }
    __syncthreads();
    for (int base = 0; base < NN; base += 1024) {
        int i = base + tid;
        int v = (i < NN) ? g_deg[i] : 0;
        sh[tid] = v;
        __syncthreads();
        for (int off = 1; off < 1024; off <<= 1) {
            int add = (tid >= off) ? sh[tid-off] : 0;
            __syncthreads();
            sh[tid] += add;
            __syncthreads();
        }
        if (i < NN) g_rowptr[i+1] = sh[tid] + carry;
        __syncthreads();
        if (tid == 0) carry += sh[1023];
        __syncthreads();
    }
}

__global__ void scatter_kernel(const int* __restrict__ idx_i) {
    int e = blockIdx.x * blockDim.x + threadIdx.x;
    if (e >= EE) return;
    if (!g_inside[e]) return;
    int i = idx_i[e];
    int p = g_rowptr[i] + atomicAdd(&g_fill[i], 1);
    g_csr[p] = e;
}

__global__ void init_kernel(const int* __restrict__ z, const float* __restrict__ emb) {
    int idx = blockIdx.x * blockDim.x + threadIdx.x;
    if (idx >= NN*FF) return;
    int n = idx / FF, f = idx % FF;
    g_sA[idx] = emb[z[n]*FF + f];
    g_vA[n*F3 + f]        = 0.0f;
    g_vA[n*F3 + FF + f]   = 0.0f;
    g_vA[n*F3 + 2*FF + f] = 0.0f;
}

// transpose-pack ALL weights into g_wT [N,K] per matrix, per layer
__global__ void pack_w_kernel(const float* __restrict__ w1, const float* __restrict__ w2,
                              const float* __restrict__ U,  const float* __restrict__ V,
                              const float* __restrict__ u1, const float* __restrict__ u2) {
    int idx = blockIdx.x * blockDim.x + threadIdx.x;
    if (idx >= LL*PS) return;
    int l = idx / PS, r = idx % PS;
    float v;
    if (r < OW2) {                    // w1T [128,128]
        int n = r >> 7, k = r & 127;
        v = w1[(size_t)l*16384 + k*128 + n];
    } else if (r < OUV) {             // w2T [384,128]
        int r2 = r - OW2; int n = r2 >> 7, k = r2 & 127;
        v = w2[(size_t)l*49152 + k*384 + n];
    } else if (r < OU1) {             // UVwT [256,128] = U|V cols
        int r2 = r - OUV; int n = r2 >> 7, k = r2 & 127;
        v = (n < 128) ? U[(size_t)l*16384 + k*128 + n]
                      : V[(size_t)l*16384 + k*128 + (n-128)];
    } else if (r < OU2) {             // u1T [128,256]
        int r2 = r - OU1; int n = r2 >> 8, k = r2 & 255;
        v = u1[(size_t)l*32768 + k*128 + n];
    } else {                          // u2T [384,128]
        int r2 = r - OU2; int n = r2 >> 7, k = r2 & 127;
        v = u2[(size_t)l*49152 + k*384 + n];
    }
    g_wT[idx] = v;
}

// ---------------- fused message kernel --------------------------------------
__global__ __launch_bounds__(128) void msg_kernel(
    const float* __restrict__ sIn, const float* __restrict__ vIn,
    const float* __restrict__ phi,
    float* __restrict__ sOut, float* __restrict__ vOut,
    const int* __restrict__ idx_j,
    const float* __restrict__ rbw, const float* __restrict__ rbb)
{
    int f = threadIdx.x;
    float wvv[RR], wss[RR], wvs[RR];
    #pragma unroll
    for (int k = 0; k < RR; k++) {
        wvv[k] = rbw[k*F3 + f];
        wss[k] = rbw[k*F3 + FF + f];
        wvs[k] = rbw[k*F3 + 2*FF + f];
    }
    float bvv = rbb[f], bss = rbb[FF+f], bvs = rbb[2*FF+f];

    for (int i = blockIdx.x; i < NN; i += gridDim.x) {
        int p0 = g_rowptr[i], p1 = g_rowptr[i+1];
        float accs = 0.f, av0 = 0.f, av1 = 0.f, av2 = 0.f;
        for (int p = p0; p < p1; p++) {
            int e = g_csr[p];
            int j = idx_j[e];
            float cut = g_cut[e];
            float d0 = g_dir[e*3+0], d1 = g_dir[e*3+1], d2 = g_dir[e*3+2];
            float Wv = bvv*cut, Ws = bss*cut, Wq = bvs*cut;
            const float* rc = &g_rbfc[e*RR];
            #pragma unroll
            for (int k = 0; k < RR; k++) {
                float r = rc[k];
                Wv += r * wvv[k];
                Ws += r * wss[k];
                Wq += r * wvs[k];
            }
            const float* ph = &phi[(size_t)j * F3];
            float pvv = ph[f]        * Wv;
            float pss = ph[FF + f]   * Ws;
            float pvs = ph[2*FF + f] * Wq;
            accs += pss;
            const float* vj = &vIn[(size_t)j * F3];
            av0 += vj[f]        * pvv + pvs * d0;
            av1 += vj[FF + f]   * pvv + pvs * d1;
            av2 += vj[2*FF + f] * pvv + pvs * d2;
        }
        sOut[(size_t)i*FF + f] = sIn[(size_t)i*FF + f] + accs;
        size_t vb = (size_t)i * F3;
        vOut[vb + f]        = vIn[vb + f]        + av0;
        vOut[vb + FF + f]   = vIn[vb + FF + f]   + av1;
        vOut[vb + 2*FF + f] = vIn[vb + 2*FF + f] + av2;
    }
}

// ---------------- x = concat(safe_norm(Vv), sfeat); Vv = g_UVv[:,128:256] ---
__global__ void buildx_kernel(const float* __restrict__ s) {
    int idx = blockIdx.x * blockDim.x + threadIdx.x;
    if (idx >= NN*2*FF) return;
    int n = idx / (2*FF), c = idx % (2*FF);
    if (c < FF) {
        size_t b = (size_t)n * 3 * 256 + 128 + c;
        float v0 = g_UVv[b], v1 = g_UVv[b + 256], v2 = g_UVv[b + 512];
        float sq = v0*v0 + v1*v1 + v2*v2;
        g_x[idx] = (sq > 0.0f) ? sqrtf(sq) : 0.0f;
    } else {
        g_x[idx] = s[(size_t)n*FF + (c - FF)];
    }
}

// ---------------- update block: reads Uv|Vv from g_UVv ----------------------
__global__ void update_kernel(float* __restrict__ s, float* __restrict__ v) {
    int idx = blockIdx.x * blockDim.x + threadIdx.x;
    if (idx >= NN*FF) return;
    int n = idx / FF, f = idx % FF;
    size_t ub = (size_t)n * 3 * 256 + f;
    float u0 = g_UVv[ub],       u1 = g_UVv[ub + 256],       u2 = g_UVv[ub + 512];
    float w0 = g_UVv[ub + 128], w1 = g_UVv[ub + 256 + 128], w2 = g_UVv[ub + 512 + 128];
    float dot = u0*w0 + u1*w1 + u2*w2;
    const float* an = &g_a[(size_t)n * F3];
    float avv = an[f], asv = an[FF + f], ass = an[2*FF + f];
    size_t b = (size_t)n * F3 + f;
    v[b]        += u0 * avv;
    v[b + FF]   += u1 * avv;
    v[b + 2*FF] += u2 * avv;
    s[idx] += ass + asv * dot;
}

__global__ void output_kernel(const float* __restrict__ s, const float* __restrict__ v,
                              float* __restrict__ out) {
    int idx = blockIdx.x * blockDim.x + threadIdx.x;
    if (idx >= NN*FF) return;
    int n = idx / FF, f = idx % FF;
    out[idx] = s[idx];
    size_t ob = (size_t)NN*FF + (size_t)idx * 3;
    size_t vb = (size_t)n * F3 + f;
    out[ob + 0] = v[vb];
    out[ob + 1] = v[vb + FF];
    out[ob + 2] = v[vb + 2*FF];
}

// ---------------- host orchestration ----------------------------------------
static inline void launch_gemm(const float* A, const float* BT, const float* bias,
                               float* C, int M, int K, int N, int act) {
    dim3 grid(N / GBN, (M + GBM - 1) / GBM);
    gemm_mma_kernel<<<grid, 256, SM_BYTES>>>(A, BT, bias, C, M, K, N, act);
}

extern "C" void kernel_launch(void* const* d_in, const int* in_sizes, int n_in,
                              void* d_out, int out_size) {
    const int*   z      = (const int*)  d_in[0];
    const float* pos    = (const float*)d_in[1];
    const int*   idx_i  = (const int*)  d_in[2];
    const int*   idx_j  = (const int*)  d_in[3];
    const float* emb    = (const float*)d_in[4];
    const float* msg_w1 = (const float*)d_in[5];
    const float* msg_b1 = (const float*)d_in[6];
    const float* msg_w2 = (const float*)d_in[7];
    const float* msg_b2 = (const float*)d_in[8];
    const float* rbf_w  = (const float*)d_in[9];
    const float* rbf_b  = (const float*)d_in[10];
    const float* upd_U  = (const float*)d_in[11];
    const float* upd_V  = (const float*)d_in[12];
    const float* upd_w1 = (const float*)d_in[13];
    const float* upd_b1 = (const float*)d_in[14];
    const float* upd_w2 = (const float*)d_in[15];
    const float* upd_b2 = (const float*)d_in[16];
    float* out = (float*)d_out;

    cudaFuncSetAttribute(gemm_mma_kernel,
                         cudaFuncAttributeMaxDynamicSharedMemorySize, SM_BYTES);

    float *sA, *sB, *vA, *vB, *phi, *hid, *wT, *UVv, *aa, *xx;
    cudaGetSymbolAddress((void**)&sA,  g_sA);
    cudaGetSymbolAddress((void**)&sB,  g_sB);
    cudaGetSymbolAddress((void**)&vA,  g_vA);
    cudaGetSymbolAddress((void**)&vB,  g_vB);
    cudaGetSymbolAddress((void**)&phi, g_phi);
    cudaGetSymbolAddress((void**)&hid, g_hid);
    cudaGetSymbolAddress((void**)&wT,  g_wT);
    cudaGetSymbolAddress((void**)&UVv, g_UVv);
    cudaGetSymbolAddress((void**)&aa,  g_a);
    cudaGetSymbolAddress((void**)&xx,  g_x);

    // ---- setup (replayed each graph iteration; deterministic) ----
    pack_w_kernel<<<(LL*PS + 255)/256, 256>>>(msg_w1, msg_w2, upd_U, upd_V, upd_w1, upd_w2);
    init_kernel<<<(NN*FF + 255)/256, 256>>>(z, emb);
    zero_counts_kernel<<<(NN + 255)/256, 256>>>();

    float* sCur = sA; float* sNxt = sB;
    float* vCur = vA; float* vNxt = vB;

    for (int l = 0; l < 3; l++) {
        const float* lw = wT + (size_t)l * PS;
        // hid = silu(s @ w1 + b1)
        launch_gemm(sCur, lw + OW1, msg_b1 + (size_t)l*FF, hid, NN, FF, 128, 1);
        if (l == 0) {
            edge_pre_kernel<<<(EE + 255)/256, 256>>>(pos, idx_i, idx_j);
            scan_kernel<<<1, 1024>>>();
            scatter_kernel<<<(EE + 255)/256, 256>>>(idx_i);
        }
        // phi = hid @ w2 + b2
        launch_gemm(hid, lw + OW2, msg_b2 + (size_t)l*F3, phi, NN, FF, 384, 0);
        // message pass
        msg_kernel<<<2000, 128>>>(sCur, vCur, phi, sNxt, vNxt, idx_j,
                                  rbf_w + (size_t)l*RR*F3, rbf_b + (size_t)l*F3);
        // [Uv | Vv] = vNxt[3N,F] @ UVw[F,2F]
        launch_gemm(vNxt, lw + OUV, nullptr, UVv, 3*NN, FF, 256, 0);
        // x = concat(||Vv||, s)
        buildx_kernel<<<(NN*2*FF + 255)/256, 256>>>(sNxt);
        // hid = silu(x @ uw1 + ub1);  a = hid @ uw2 + ub2
        launch_gemm(xx, lw + OU1, upd_b1 + (size_t)l*FF, hid, NN, 2*FF, 128, 1);
        launch_gemm(hid, lw + OU2, upd_b2 + (size_t)l*F3, aa, NN, FF, 384, 0);
        // in-place update
        update_kernel<<<(NN*FF + 255)/256, 256>>>(sNxt, vNxt);

        float* t;
        t = sCur; sCur = sNxt; sNxt = t;
        t = vCur; vCur = vNxt; vNxt = t;
    }

    output_kernel<<<(NN*FF + 255)/256, 256>>>(sCur, vCur, out);
}

// round 5
// speedup vs baseline: 1.1799x; 1.0400x over previous
#include <cuda_runtime.h>
#include <cstdint>
#include <math.h>

#ifndef M_PI
#define M_PI 3.14159265358979323846
#endif

#define NN 10000
#define EE 160000
#define FF 128
#define RR 20
#define F3 (3*FF)
#define CUT_D 3.0f
#define LL 3

// per-layer packed transposed-weight stride (floats)
#define PS 180224
#define OW1 0          /* w1T  [128,128] */
#define OW2 16384      /* w2T  [384,128] */
#define OUV 65536      /* UVwT [256,128] */
#define OU1 98304      /* u1T  [128,256] */
#define OU2 131072     /* u2T  [384,128] */

// ---------------- scratch (device globals; no allocation allowed) ----------
__device__ float g_rbfc[EE*RR];
__device__ float g_cut[EE];
__device__ float g_dir[EE*3];
__device__ int   g_inside[EE];
__device__ int   g_deg[NN];
__device__ int   g_rowptr[NN+1];
__device__ int   g_fill[NN];
__device__ int   g_csr[EE];
__device__ float g_sA[NN*FF], g_sB[NN*FF];
__device__ float g_vA[NN*3*FF], g_vB[NN*3*FF];   // stored [N,3,F]
__device__ float g_phi[NN*F3];
__device__ float g_hid[NN*FF];
__device__ float g_wT[LL*PS];                    // all weights transposed to [N,K]
__device__ float g_UVv[NN*3*2*FF];               // [3N][256]: Uv | Vv
__device__ float g_x[NN*2*FF];
__device__ float g_a[NN*F3];

// ================= tf32 mma.sync GEMM (cp.async pipelined) ==================
// C[M,N] = act(A[M,K] @ BT[N,K]^T + bias). N mult of 64, K mult of 32.
// Raw fp32 in smem; 3xTF32 hi/lo split done at fragment-load time.
#define GBM 128
#define GBN 64
#define GBK 32
#define APAD 36                         /* row stride in floats */
#define ASZ (128*APAD)                  /* A stage floats */
#define BSZ (64*APAD)                   /* B stage floats */
#define STG (ASZ+BSZ)                   /* one stage */
#define SM_BYTES (2*STG*4)

__device__ __forceinline__ uint32_t smem_u32(const void* p) {
    uint32_t a;
    asm("{ .reg .u64 t; cvta.to.shared.u64 t, %1; cvt.u32.u64 %0, t; }"
        : "=r"(a) : "l"(p));
    return a;
}
__device__ __forceinline__ void cp_async16(uint32_t dst, const void* src, int srcBytes) {
    asm volatile("cp.async.cg.shared.global [%0], [%1], 16, %2;"
                 :: "r"(dst), "l"(src), "r"(srcBytes) : "memory");
}
__device__ __forceinline__ void cp_commit() {
    asm volatile("cp.async.commit_group;" ::: "memory");
}
__device__ __forceinline__ void cp_wait1() {
    asm volatile("cp.async.wait_group 1;" ::: "memory");
}
__device__ __forceinline__ void cp_wait0() {
    asm volatile("cp.async.wait_group 0;" ::: "memory");
}

__device__ __forceinline__ void mma_tf32(float* c, const uint32_t* a, const uint32_t* b) {
    asm volatile(
        "mma.sync.aligned.m16n8k8.row.col.f32.tf32.tf32.f32 "
        "{%0,%1,%2,%3}, {%4,%5,%6,%7}, {%8,%9}, {%0,%1,%2,%3};"
        : "+f"(c[0]), "+f"(c[1]), "+f"(c[2]), "+f"(c[3])
        : "r"(a[0]), "r"(a[1]), "r"(a[2]), "r"(a[3]), "r"(b[0]), "r"(b[1]));
}

__global__ __launch_bounds__(256, 2) void gemm_mma_kernel(
    const float* __restrict__ A, const float* __restrict__ BT,
    const float* __restrict__ bias, float* __restrict__ C,
    int M, int K, int N, int act)
{
    extern __shared__ float sm[];
    uint32_t sb = smem_u32(sm);
    int tid  = threadIdx.x;
    int lane = tid & 31;
    int warp = tid >> 5;
    int wm = warp & 3;
    int wn = warp >> 2;
    int g  = lane >> 2;
    int t  = lane & 3;
    int rowBase = blockIdx.y * GBM;
    int colBase = blockIdx.x * GBN;

    // loader indices
    int arow = tid >> 3;            // +256-thread strides below
    int akq  = tid & 7;

    float acc[2][4][4];
    #pragma unroll
    for (int mt = 0; mt < 2; mt++)
        #pragma unroll
        for (int nt = 0; nt < 4; nt++)
            #pragma unroll
            for (int q = 0; q < 4; q++) acc[mt][nt][q] = 0.0f;

    const uint32_t MHI = 0xFFFFE000u;
    int chunks = K >> 5;

    // ---- async loaders ----
    auto loadChunk = [&](int c, int s) {
        int k0 = c << 5;
        uint32_t abase = sb + (uint32_t)(s * STG) * 4u;
        #pragma unroll
        for (int it = 0; it < 4; it++) {
            int row = arow + it * 32;
            int gr = rowBase + row;
            int ok = (gr < M);
            const float* src = &A[(size_t)(ok ? gr : 0) * K + k0 + akq * 4];
            cp_async16(abase + (uint32_t)(row * APAD + akq * 4) * 4u, src, ok ? 16 : 0);
        }
        uint32_t bbase = abase + (uint32_t)ASZ * 4u;
        #pragma unroll
        for (int it = 0; it < 2; it++) {
            int row = arow + it * 32;
            const float* src = &BT[(size_t)(colBase + row) * K + k0 + akq * 4];
            cp_async16(bbase + (uint32_t)(row * APAD + akq * 4) * 4u, src, 16);
        }
        cp_commit();
    };

    loadChunk(0, 0);

    for (int c = 0; c < chunks; c++) {
        int cur = c & 1;
        if (c + 1 < chunks) {
            loadChunk(c + 1, (c + 1) & 1);
            cp_wait1();
        } else {
            cp_wait0();
        }
        __syncthreads();

        const float* sA_ = &sm[cur * STG];
        const float* sB_ = &sm[cur * STG + ASZ];

        #pragma unroll
        for (int ks = 0; ks < 4; ks++) {
            int kk = ks * 8;
            uint32_t aH[2][4], aL[2][4], bH[4][2], bL[4][2];
            #pragma unroll
            for (int mt = 0; mt < 2; mt++) {
                int base = (wm*32 + mt*16 + g) * APAD + kk + t;
                float a0 = sA_[base];
                float a1 = sA_[base + 8*APAD];
                float a2 = sA_[base + 4];
                float a3 = sA_[base + 8*APAD + 4];
                float h0 = __uint_as_float(__float_as_uint(a0) & MHI);
                float h1 = __uint_as_float(__float_as_uint(a1) & MHI);
                float h2 = __uint_as_float(__float_as_uint(a2) & MHI);
                float h3 = __uint_as_float(__float_as_uint(a3) & MHI);
                aH[mt][0] = __float_as_uint(h0); aL[mt][0] = __float_as_uint(a0 - h0);
                aH[mt][1] = __float_as_uint(h1); aL[mt][1] = __float_as_uint(a1 - h1);
                aH[mt][2] = __float_as_uint(h2); aL[mt][2] = __float_as_uint(a2 - h2);
                aH[mt][3] = __float_as_uint(h3); aL[mt][3] = __float_as_uint(a3 - h3);
            }
            #pragma unroll
            for (int nt = 0; nt < 4; nt++) {
                int base = (wn*32 + nt*8 + g) * APAD + kk + t;
                float b0 = sB_[base];
                float b1 = sB_[base + 4];
                float h0 = __uint_as_float(__float_as_uint(b0) & MHI);
                float h1 = __uint_as_float(__float_as_uint(b1) & MHI);
                bH[nt][0] = __float_as_uint(h0); bL[nt][0] = __float_as_uint(b0 - h0);
                bH[nt][1] = __float_as_uint(h1); bL[nt][1] = __float_as_uint(b1 - h1);
            }
            #pragma unroll
            for (int mt = 0; mt < 2; mt++)
                #pragma unroll
                for (int nt = 0; nt < 4; nt++) {
                    mma_tf32(acc[mt][nt], aH[mt], bH[nt]);
                    mma_tf32(acc[mt][nt], aH[mt], bL[nt]);
                    mma_tf32(acc[mt][nt], aL[mt], bH[nt]);
                }
        }
        __syncthreads();
    }

    // ---- epilogue ----
    #pragma unroll
    for (int mt = 0; mt < 2; mt++) {
        int r0 = rowBase + wm*32 + mt*16 + g;
        int r1 = r0 + 8;
        #pragma unroll
        for (int nt = 0; nt < 4; nt++) {
            int cc = colBase + wn*32 + nt*8 + t*2;
            float b0 = 0.f, b1 = 0.f;
            if (bias) { b0 = bias[cc]; b1 = bias[cc+1]; }
            float o0 = acc[mt][nt][0] + b0;
            float o1 = acc[mt][nt][1] + b1;
            float o2 = acc[mt][nt][2] + b0;
            float o3 = acc[mt][nt][3] + b1;
            if (act == 1) {
                o0 = o0 / (1.0f + expf(-o0));
                o1 = o1 / (1.0f + expf(-o1));
                o2 = o2 / (1.0f + expf(-o2));
                o3 = o3 / (1.0f + expf(-o3));
            }
            if (r0 < M) *(float2*)&C[(size_t)r0*N + cc] = make_float2(o0, o1);
            if (r1 < M) *(float2*)&C[(size_t)r1*N + cc] = make_float2(o2, o3);
        }
    }
}

// ================= graph-structure + elementwise kernels =====================
__global__ void zero_counts_kernel() {
    int i = blockIdx.x * blockDim.x + threadIdx.x;
    if (i < NN) { g_deg[i] = 0; g_fill[i] = 0; }
}

__global__ void edge_pre_kernel(const float* __restrict__ pos,
                                const int* __restrict__ idx_i,
                                const int* __restrict__ idx_j) {
    int e = blockIdx.x * blockDim.x + threadIdx.x;
    if (e >= EE) return;
    int i = idx_i[e], j = idx_j[e];
    float rx = pos[j*3+0] - pos[i*3+0];
    float ry = pos[j*3+1] - pos[i*3+1];
    float rz = pos[j*3+2] - pos[i*3+2];
    float sq = rx*rx + ry*ry + rz*rz;
    float d  = sqrtf(sq);
    float inv = 1.0f / d;
    g_dir[e*3+0] = rx*inv;
    g_dir[e*3+1] = ry*inv;
    g_dir[e*3+2] = rz*inv;
    int ins = (d < CUT_D) ? 1 : 0;
    float base = (float)M_PI * d / CUT_D;
    float s1, c1;
    sincosf(base, &s1, &c1);
    float cut = ins ? 0.5f * (c1 + 1.0f) : 0.0f;
    g_cut[e] = cut;
    g_inside[e] = ins;
    float ic = inv * cut;
    float twoc = 2.0f * c1;
    float sk = s1, skm1 = 0.0f;
    #pragma unroll
    for (int k = 0; k < RR; k++) {
        g_rbfc[e*RR+k] = sk * ic;
        float nxt = twoc * sk - skm1;
        skm1 = sk; sk = nxt;
    }
    if (ins) atomicAdd(&g_deg[i], 1);
}

__global__ void scan_kernel() {
    __shared__ int sh[1024];
    __shared__ int carry;
    int tid = threadIdx.x;
    if (tid == 0) { carry = 0; g_rowptr[0] = 0; }
    __syncthreads();
    for (int base = 0; base < NN; base += 1024) {
        int i = base + tid;
        int v = (i < NN) ? g_deg[i] : 0;
        sh[tid] = v;
        __syncthreads();
        for (int off = 1; off < 1024; off <<= 1) {
            int add = (tid >= off) ? sh[tid-off] : 0;
            __syncthreads();
            sh[tid] += add;
            __syncthreads();
        }
        if (i < NN) g_rowptr[i+1] = sh[tid] + carry;
        __syncthreads();
        if (tid == 0) carry += sh[1023];
        __syncthreads();
    }
}

__global__ void scatter_kernel(const int* __restrict__ idx_i) {
    int e = blockIdx.x * blockDim.x + threadIdx.x;
    if (e >= EE) return;
    if (!g_inside[e]) return;
    int i = idx_i[e];
    int p = g_rowptr[i] + atomicAdd(&g_fill[i], 1);
    g_csr[p] = e;
}

__global__ void init_kernel(const int* __restrict__ z, const float* __restrict__ emb) {
    int idx = blockIdx.x * blockDim.x + threadIdx.x;
    if (idx >= NN*FF) return;
    int n = idx / FF, f = idx % FF;
    g_sA[idx] = emb[z[n]*FF + f];
    g_vA[n*F3 + f]        = 0.0f;
    g_vA[n*F3 + FF + f]   = 0.0f;
    g_vA[n*F3 + 2*FF + f] = 0.0f;
}

// transpose-pack ALL weights into g_wT [N,K] per matrix, per layer
__global__ void pack_w_kernel(const float* __restrict__ w1, const float* __restrict__ w2,
                              const float* __restrict__ U,  const float* __restrict__ V,
                              const float* __restrict__ u1, const float* __restrict__ u2) {
    int idx = blockIdx.x * blockDim.x + threadIdx.x;
    if (idx >= LL*PS) return;
    int l = idx / PS, r = idx % PS;
    float v;
    if (r < OW2) {                    // w1T [128,128]
        int n = r >> 7, k = r & 127;
        v = w1[(size_t)l*16384 + k*128 + n];
    } else if (r < OUV) {             // w2T [384,128]
        int r2 = r - OW2; int n = r2 >> 7, k = r2 & 127;
        v = w2[(size_t)l*49152 + k*384 + n];
    } else if (r < OU1) {             // UVwT [256,128] = U|V cols
        int r2 = r - OUV; int n = r2 >> 7, k = r2 & 127;
        v = (n < 128) ? U[(size_t)l*16384 + k*128 + n]
                      : V[(size_t)l*16384 + k*128 + (n-128)];
    } else if (r < OU2) {             // u1T [128,256]
        int r2 = r - OU1; int n = r2 >> 8, k = r2 & 255;
        v = u1[(size_t)l*32768 + k*128 + n];
    } else {                          // u2T [384,128]
        int r2 = r - OU2; int n = r2 >> 7, k = r2 & 127;
        v = u2[(size_t)l*49152 + k*384 + n];
    }
    g_wT[idx] = v;
}

// ---------------- fused message kernel --------------------------------------
__global__ __launch_bounds__(128) void msg_kernel(
    const float* __restrict__ sIn, const float* __restrict__ vIn,
    const float* __restrict__ phi,
    float* __restrict__ sOut, float* __restrict__ vOut,
    const int* __restrict__ idx_j,
    const float* __restrict__ rbw, const float* __restrict__ rbb)
{
    int f = threadIdx.x;
    float wvv[RR], wss[RR], wvs[RR];
    #pragma unroll
    for (int k = 0; k < RR; k++) {
        wvv[k] = rbw[k*F3 + f];
        wss[k] = rbw[k*F3 + FF + f];
        wvs[k] = rbw[k*F3 + 2*FF + f];
    }
    float bvv = rbb[f], bss = rbb[FF+f], bvs = rbb[2*FF+f];

    for (int i = blockIdx.x; i < NN; i += gridDim.x) {
        int p0 = g_rowptr[i], p1 = g_rowptr[i+1];
        float accs = 0.f, av0 = 0.f, av1 = 0.f, av2 = 0.f;
        for (int p = p0; p < p1; p++) {
            int e = g_csr[p];
            int j = idx_j[e];
            float cut = g_cut[e];
            float d0 = g_dir[e*3+0], d1 = g_dir[e*3+1], d2 = g_dir[e*3+2];
            float Wv = bvv*cut, Ws = bss*cut, Wq = bvs*cut;
            const float* rc = &g_rbfc[e*RR];
            #pragma unroll
            for (int k = 0; k < RR; k++) {
                float r = rc[k];
                Wv += r * wvv[k];
                Ws += r * wss[k];
                Wq += r * wvs[k];
            }
            const float* ph = &phi[(size_t)j * F3];
            float pvv = ph[f]        * Wv;
            float pss = ph[FF + f]   * Ws;
            float pvs = ph[2*FF + f] * Wq;
            accs += pss;
            const float* vj = &vIn[(size_t)j * F3];
            av0 += vj[f]        * pvv + pvs * d0;
            av1 += vj[FF + f]   * pvv + pvs * d1;
            av2 += vj[2*FF + f] * pvv + pvs * d2;
        }
        sOut[(size_t)i*FF + f] = sIn[(size_t)i*FF + f] + accs;
        size_t vb = (size_t)i * F3;
        vOut[vb + f]        = vIn[vb + f]        + av0;
        vOut[vb + FF + f]   = vIn[vb + FF + f]   + av1;
        vOut[vb + 2*FF + f] = vIn[vb + 2*FF + f] + av2;
    }
}

// ---------------- x = concat(safe_norm(Vv), sfeat); Vv = g_UVv[:,128:256] ---
__global__ void buildx_kernel(const float* __restrict__ s) {
    int idx = blockIdx.x * blockDim.x + threadIdx.x;
    if (idx >= NN*2*FF) return;
    int n = idx / (2*FF), c = idx % (2*FF);
    if (c < FF) {
        size_t b = (size_t)n * 3 * 256 + 128 + c;
        float v0 = g_UVv[b], v1 = g_UVv[b + 256], v2 = g_UVv[b + 512];
        float sq = v0*v0 + v1*v1 + v2*v2;
        g_x[idx] = (sq > 0.0f) ? sqrtf(sq) : 0.0f;
    } else {
        g_x[idx] = s[(size_t)n*FF + (c - FF)];
    }
}

// ---------------- update block: reads Uv|Vv from g_UVv ----------------------
__global__ void update_kernel(float* __restrict__ s, float* __restrict__ v) {
    int idx = blockIdx.x * blockDim.x + threadIdx.x;
    if (idx >= NN*FF) return;
    int n = idx / FF, f = idx % FF;
    size_t ub = (size_t)n * 3 * 256 + f;
    float u0 = g_UVv[ub],       u1 = g_UVv[ub + 256],       u2 = g_UVv[ub + 512];
    float w0 = g_UVv[ub + 128], w1 = g_UVv[ub + 256 + 128], w2 = g_UVv[ub + 512 + 128];
    float dot = u0*w0 + u1*w1 + u2*w2;
    const float* an = &g_a[(size_t)n * F3];
    float avv = an[f], asv = an[FF + f], ass = an[2*FF + f];
    size_t b = (size_t)n * F3 + f;
    v[b]        += u0 * avv;
    v[b + FF]   += u1 * avv;
    v[b + 2*FF] += u2 * avv;
    s[idx] += ass + asv * dot;
}

__global__ void output_kernel(const float* __restrict__ s, const float* __restrict__ v,
                              float* __restrict__ out) {
    int idx = blockIdx.x * blockDim.x + threadIdx.x;
    if (idx >= NN*FF) return;
    int n = idx / FF, f = idx % FF;
    out[idx] = s[idx];
    size_t ob = (size_t)NN*FF + (size_t)idx * 3;
    size_t vb = (size_t)n * F3 + f;
    out[ob + 0] = v[vb];
    out[ob + 1] = v[vb + FF];
    out[ob + 2] = v[vb + 2*FF];
}

// ---------------- host orchestration ----------------------------------------
static inline void launch_gemm(const float* A, const float* BT, const float* bias,
                               float* C, int M, int K, int N, int act) {
    dim3 grid(N / GBN, (M + GBM - 1) / GBM);
    gemm_mma_kernel<<<grid, 256, SM_BYTES>>>(A, BT, bias, C, M, K, N, act);
}

extern "C" void kernel_launch(void* const* d_in, const int* in_sizes, int n_in,
                              void* d_out, int out_size) {
    const int*   z      = (const int*)  d_in[0];
    const float* pos    = (const float*)d_in[1];
    const int*   idx_i  = (const int*)  d_in[2];
    const int*   idx_j  = (const int*)  d_in[3];
    const float* emb    = (const float*)d_in[4];
    const float* msg_w1 = (const float*)d_in[5];
    const float* msg_b1 = (const float*)d_in[6];
    const float* msg_w2 = (const float*)d_in[7];
    const float* msg_b2 = (const float*)d_in[8];
    const float* rbf_w  = (const float*)d_in[9];
    const float* rbf_b  = (const float*)d_in[10];
    const float* upd_U  = (const float*)d_in[11];
    const float* upd_V  = (const float*)d_in[12];
    const float* upd_w1 = (const float*)d_in[13];
    const float* upd_b1 = (const float*)d_in[14];
    const float* upd_w2 = (const float*)d_in[15];
    const float* upd_b2 = (const float*)d_in[16];
    float* out = (float*)d_out;

    cudaFuncSetAttribute(gemm_mma_kernel,
                         cudaFuncAttributeMaxDynamicSharedMemorySize, SM_BYTES);

    float *sA, *sB, *vA, *vB, *phi, *hid, *wT, *UVv, *aa, *xx;
    cudaGetSymbolAddress((void**)&sA,  g_sA);
    cudaGetSymbolAddress((void**)&sB,  g_sB);
    cudaGetSymbolAddress((void**)&vA,  g_vA);
    cudaGetSymbolAddress((void**)&vB,  g_vB);
    cudaGetSymbolAddress((void**)&phi, g_phi);
    cudaGetSymbolAddress((void**)&hid, g_hid);
    cudaGetSymbolAddress((void**)&wT,  g_wT);
    cudaGetSymbolAddress((void**)&UVv, g_UVv);
    cudaGetSymbolAddress((void**)&aa,  g_a);
    cudaGetSymbolAddress((void**)&xx,  g_x);

    // ---- setup (replayed each graph iteration; deterministic) ----
    pack_w_kernel<<<(LL*PS + 255)/256, 256>>>(msg_w1, msg_w2, upd_U, upd_V, upd_w1, upd_w2);
    init_kernel<<<(NN*FF + 255)/256, 256>>>(z, emb);
    zero_counts_kernel<<<(NN + 255)/256, 256>>>();

    float* sCur = sA; float* sNxt = sB;
    float* vCur = vA; float* vNxt = vB;

    for (int l = 0; l < 3; l++) {
        const float* lw = wT + (size_t)l * PS;
        // hid = silu(s @ w1 + b1)
        launch_gemm(sCur, lw + OW1, msg_b1 + (size_t)l*FF, hid, NN, FF, 128, 1);
        if (l == 0) {
            edge_pre_kernel<<<(EE + 255)/256, 256>>>(pos, idx_i, idx_j);
            scan_kernel<<<1, 1024>>>();
            scatter_kernel<<<(EE + 255)/256, 256>>>(idx_i);
        }
        // phi = hid @ w2 + b2
        launch_gemm(hid, lw + OW2, msg_b2 + (size_t)l*F3, phi, NN, FF, 384, 0);
        // message pass
        msg_kernel<<<2000, 128>>>(sCur, vCur, phi, sNxt, vNxt, idx_j,
                                  rbf_w + (size_t)l*RR*F3, rbf_b + (size_t)l*F3);
        // [Uv | Vv] = vNxt[3N,F] @ UVw[F,2F]
        launch_gemm(vNxt, lw + OUV, nullptr, UVv, 3*NN, FF, 256, 0);
        // x = concat(||Vv||, s)
        buildx_kernel<<<(NN*2*FF + 255)/256, 256>>>(sNxt);
        // hid = silu(x @ uw1 + ub1);  a = hid @ uw2 + ub2
        launch_gemm(xx, lw + OU1, upd_b1 + (size_t)l*FF, hid, NN, 2*FF, 128, 1);
        launch_gemm(hid, lw + OU2, upd_b2 + (size_t)l*F3, aa, NN, FF, 384, 0);
        // in-place update
        update_kernel<<<(NN*FF + 255)/256, 256>>>(sNxt, vNxt);

        float* t;
        t = sCur; sCur = sNxt; sNxt = t;
        t = vCur; vCur = vNxt; vNxt = t;
    }

    output_kernel<<<(NN*FF + 255)/256, 256>>>(sCur, vCur, out);
}

// round 6
// speedup vs baseline: 1.2352x; 1.0468x over previous
#include <cuda_runtime.h>
#include <cstdint>
#include <math.h>

#ifndef M_PI
#define M_PI 3.14159265358979323846
#endif

#define NN 10000
#define EE 160000
#define FF 128
#define RR 20
#define F3 (3*FF)
#define CUT_D 3.0f
#define LL 3

// per-layer packed transposed-weight stride (floats)
#define PS 180224
#define OW1 0          /* w1T  [128,128] */
#define OW2 16384      /* w2T  [384,128] */
#define OUV 65536      /* UVwT [256,128] */
#define OU1 98304      /* u1T  [128,256] */
#define OU2 131072     /* u2T  [384,128] */

// ---------------- scratch (device globals; no allocation allowed) ----------
__device__ float g_rbfc[EE*RR];
__device__ float g_cut[EE];
__device__ float g_dir[EE*3];
__device__ int   g_inside[EE];
__device__ int   g_deg[NN];
__device__ int   g_rowptr[NN+1];
__device__ int   g_fill[NN];
__device__ int   g_csr[EE];
__device__ float g_sA[NN*FF], g_sB[NN*FF];
__device__ float g_vA[NN*3*FF], g_vB[NN*3*FF];   // stored [N,3,F]
__device__ float g_phi[NN*F3];
__device__ float g_hid[NN*FF];
__device__ float g_wT[LL*PS];                    // all weights transposed to [N,K]
__device__ float g_UVv[NN*3*2*FF];               // [3N][256]: Uv | Vv
__device__ float g_x[NN*2*FF];
__device__ float g_a[NN*F3];

// ================= bf16x3 mma.sync GEMM =====================================
// C[M,N] = act(A[M,K] @ BT[N,K]^T + bias). N mult of 64, K mult of 32.
// fp32 -> bf16 hi/lo split at smem-store time; D ~= aH*bH + aH*bL + aL*bH.
#define GBM 64
#define GBN 64
#define GBK 32
#define USTRIDE 20                       /* uints per row: 16 data + 4 pad */
#define TSZ (64*USTRIDE)                 /* one matrix tile, uints */
#define STGU (4*TSZ)                     /* AH AL BH BL */
#define SMU (2*STGU)                     /* double buffered: 40 KB */

__device__ __forceinline__ uint32_t bf16bits_hi(float x) {
    uint32_t u = __float_as_uint(x);
    return (u + 0x7FFFu + ((u >> 16) & 1u)) & 0xFFFF0000u;   // float bits of rn(bf16)
}
// split two floats into packed bf16x2 hi and lo
__device__ __forceinline__ void split2(float x, float y, uint32_t& hi2, uint32_t& lo2) {
    uint32_t hx = bf16bits_hi(x);
    uint32_t hy = bf16bits_hi(y);
    float lx = x - __uint_as_float(hx);
    float ly = y - __uint_as_float(hy);
    uint32_t lxb = bf16bits_hi(lx);
    uint32_t lyb = bf16bits_hi(ly);
    hi2 = (hx >> 16) | hy;
    lo2 = (lxb >> 16) | lyb;
}

__device__ __forceinline__ void mma_bf16(float* c, uint32_t a0, uint32_t a1, uint32_t b0) {
    asm volatile(
        "mma.sync.aligned.m16n8k8.row.col.f32.bf16.bf16.f32 "
        "{%0,%1,%2,%3}, {%4,%5}, {%6}, {%0,%1,%2,%3};"
        : "+f"(c[0]), "+f"(c[1]), "+f"(c[2]), "+f"(c[3])
        : "r"(a0), "r"(a1), "r"(b0));
}

__global__ __launch_bounds__(256) void gemm_bf16_kernel(
    const float* __restrict__ A, const float* __restrict__ BT,
    const float* __restrict__ bias, float* __restrict__ C,
    int M, int K, int N, int act)
{
    __shared__ uint32_t sm[SMU];
    uint32_t* AH0 = sm;                 // per stage: [AH][AL][BH][BL]
    int tid  = threadIdx.x;
    int lane = tid & 31;
    int warp = tid >> 5;
    int wm = warp & 1;                  // 2 warps along M
    int wn = warp >> 1;                 // 4 warps along N
    int g  = lane >> 2;                 // 0..7
    int t  = lane & 3;                  // 0..3
    int rowBase = blockIdx.y * GBM;
    int colBase = blockIdx.x * GBN;

    // loader: 512 float4 per matrix per chunk, 2 per thread
    int lrow0 = tid >> 3;               // 0..31
    int lkq   = tid & 7;                // 0..7 (float4 within 32-k chunk)

    float acc[2][2][4];
    #pragma unroll
    for (int mt = 0; mt < 2; mt++)
        #pragma unroll
        for (int nt = 0; nt < 2; nt++)
            #pragma unroll
            for (int q = 0; q < 4; q++) acc[mt][nt][q] = 0.0f;

    int chunks = K >> 5;
    float4 pa[2], pb[2];

    auto ldg = [&](int c) {
        int k0 = c << 5;
        #pragma unroll
        for (int it = 0; it < 2; it++) {
            int row = lrow0 + it * 32;
            int gr = rowBase + row;
            pa[it] = (gr < M) ? *(const float4*)&A[(size_t)gr * K + k0 + lkq * 4]
                              : make_float4(0.f, 0.f, 0.f, 0.f);
            pb[it] = *(const float4*)&BT[(size_t)(colBase + row) * K + k0 + lkq * 4];
        }
    };
    auto sts = [&](int s) {
        uint32_t* base = sm + s * STGU;
        #pragma unroll
        for (int it = 0; it < 2; it++) {
            int row = lrow0 + it * 32;
            int uo = row * USTRIDE + lkq * 2;
            uint32_t h0, l0, h1, l1;
            split2(pa[it].x, pa[it].y, h0, l0);
            split2(pa[it].z, pa[it].w, h1, l1);
            base[uo]           = h0;  base[uo + 1]           = h1;
            base[TSZ + uo]     = l0;  base[TSZ + uo + 1]     = l1;
            split2(pb[it].x, pb[it].y, h0, l0);
            split2(pb[it].z, pb[it].w, h1, l1);
            base[2*TSZ + uo]   = h0;  base[2*TSZ + uo + 1]   = h1;
            base[3*TSZ + uo]   = l0;  base[3*TSZ + uo + 1]   = l1;
        }
    };

    ldg(0); sts(0);

    for (int c = 0; c < chunks; c++) {
        __syncthreads();
        if (c + 1 < chunks) ldg(c + 1);

        const uint32_t* st = sm + (c & 1) * STGU;
        const uint32_t* sAH = st;
        const uint32_t* sAL = st + TSZ;
        const uint32_t* sBH = st + 2*TSZ;
        const uint32_t* sBL = st + 3*TSZ;

        #pragma unroll
        for (int ks = 0; ks < 4; ks++) {
            uint32_t aH[2][2], aL[2][2], bH[2], bL[2];
            #pragma unroll
            for (int mt = 0; mt < 2; mt++) {
                int uo = (wm*32 + mt*16 + g) * USTRIDE + ks*4 + t;
                aH[mt][0] = sAH[uo];
                aH[mt][1] = sAH[uo + 8*USTRIDE];
                aL[mt][0] = sAL[uo];
                aL[mt][1] = sAL[uo + 8*USTRIDE];
            }
            #pragma unroll
            for (int nt = 0; nt < 2; nt++) {
                int uo = (wn*16 + nt*8 + g) * USTRIDE + ks*4 + t;
                bH[nt] = sBH[uo];
                bL[nt] = sBL[uo];
            }
            #pragma unroll
            for (int mt = 0; mt < 2; mt++)
                #pragma unroll
                for (int nt = 0; nt < 2; nt++) {
                    mma_bf16(acc[mt][nt], aH[mt][0], aH[mt][1], bH[nt]);
                    mma_bf16(acc[mt][nt], aH[mt][0], aH[mt][1], bL[nt]);
                    mma_bf16(acc[mt][nt], aL[mt][0], aL[mt][1], bH[nt]);
                }
        }
        if (c + 1 < chunks) sts((c + 1) & 1);
    }

    // ---- epilogue ----
    #pragma unroll
    for (int mt = 0; mt < 2; mt++) {
        int r0 = rowBase + wm*32 + mt*16 + g;
        int r1 = r0 + 8;
        #pragma unroll
        for (int nt = 0; nt < 2; nt++) {
            int cc = colBase + wn*16 + nt*8 + t*2;
            float b0 = 0.f, b1 = 0.f;
            if (bias) { b0 = bias[cc]; b1 = bias[cc+1]; }
            float o0 = acc[mt][nt][0] + b0;
            float o1 = acc[mt][nt][1] + b1;
            float o2 = acc[mt][nt][2] + b0;
            float o3 = acc[mt][nt][3] + b1;
            if (act == 1) {
                o0 = o0 / (1.0f + expf(-o0));
                o1 = o1 / (1.0f + expf(-o1));
                o2 = o2 / (1.0f + expf(-o2));
                o3 = o3 / (1.0f + expf(-o3));
            }
            if (r0 < M) *(float2*)&C[(size_t)r0*N + cc] = make_float2(o0, o1);
            if (r1 < M) *(float2*)&C[(size_t)r1*N + cc] = make_float2(o2, o3);
        }
    }
}

// ================= graph-structure + elementwise kernels =====================
__global__ void zero_counts_kernel() {
    int i = blockIdx.x * blockDim.x + threadIdx.x;
    if (i < NN) { g_deg[i] = 0; g_fill[i] = 0; }
}

__global__ void edge_pre_kernel(const float* __restrict__ pos,
                                const int* __restrict__ idx_i,
                                const int* __restrict__ idx_j) {
    int e = blockIdx.x * blockDim.x + threadIdx.x;
    if (e >= EE) return;
    int i = idx_i[e], j = idx_j[e];
    float rx = pos[j*3+0] - pos[i*3+0];
    float ry = pos[j*3+1] - pos[i*3+1];
    float rz = pos[j*3+2] - pos[i*3+2];
    float sq = rx*rx + ry*ry + rz*rz;
    float d  = sqrtf(sq);
    float inv = 1.0f / d;
    g_dir[e*3+0] = rx*inv;
    g_dir[e*3+1] = ry*inv;
    g_dir[e*3+2] = rz*inv;
    int ins = (d < CUT_D) ? 1 : 0;
    float base = (float)M_PI * d / CUT_D;
    float s1, c1;
    sincosf(base, &s1, &c1);
    float cut = ins ? 0.5f * (c1 + 1.0f) : 0.0f;
    g_cut[e] = cut;
    g_inside[e] = ins;
    float ic = inv * cut;
    float twoc = 2.0f * c1;
    float sk = s1, skm1 = 0.0f;
    #pragma unroll
    for (int k = 0; k < RR; k++) {
        g_rbfc[e*RR+k] = sk * ic;
        float nxt = twoc * sk - skm1;
        skm1 = sk; sk = nxt;
    }
    if (ins) atomicAdd(&g_deg[i], 1);
}

__global__ void scan_kernel() {
    __shared__ int sh[1024];
    __shared__ int carry;
    int tid = threadIdx.x;
    if (tid == 0) { carry = 0; g_rowptr[0] = 0; }
    __syncthreads();
    for (int base = 0; base < NN; base += 1024) {
        int i = base + tid;
        int v = (i < NN) ? g_deg[i] : 0;
        sh[tid] = v;
        __syncthreads();
        for (int off = 1; off < 1024; off <<= 1) {
            int add = (tid >= off) ? sh[tid-off] : 0;
            __syncthreads();
            sh[tid] += add;
            __syncthreads();
        }
        if (i < NN) g_rowptr[i+1] = sh[tid] + carry;
        __syncthreads();
        if (tid == 0) carry += sh[1023];
        __syncthreads();
    }
}

__global__ void scatter_kernel(const int* __restrict__ idx_i) {
    int e = blockIdx.x * blockDim.x + threadIdx.x;
    if (e >= EE) return;
    if (!g_inside[e]) return;
    int i = idx_i[e];
    int p = g_rowptr[i] + atomicAdd(&g_fill[i], 1);
    g_csr[p] = e;
}

__global__ void init_kernel(const int* __restrict__ z, const float* __restrict__ emb) {
    int idx = blockIdx.x * blockDim.x + threadIdx.x;
    if (idx >= NN*FF) return;
    int n = idx / FF, f = idx % FF;
    g_sA[idx] = emb[z[n]*FF + f];
    g_vA[n*F3 + f]        = 0.0f;
    g_vA[n*F3 + FF + f]   = 0.0f;
    g_vA[n*F3 + 2*FF + f] = 0.0f;
}

// transpose-pack ALL weights into g_wT [N,K] per matrix, per layer
__global__ void pack_w_kernel(const float* __restrict__ w1, const float* __restrict__ w2,
                              const float* __restrict__ U,  const float* __restrict__ V,
                              const float* __restrict__ u1, const float* __restrict__ u2) {
    int idx = blockIdx.x * blockDim.x + threadIdx.x;
    if (idx >= LL*PS) return;
    int l = idx / PS, r = idx % PS;
    float v;
    if (r < OW2) {                    // w1T [128,128]
        int n = r >> 7, k = r & 127;
        v = w1[(size_t)l*16384 + k*128 + n];
    } else if (r < OUV) {             // w2T [384,128]
        int r2 = r - OW2; int n = r2 >> 7, k = r2 & 127;
        v = w2[(size_t)l*49152 + k*384 + n];
    } else if (r < OU1) {             // UVwT [256,128] = U|V cols
        int r2 = r - OUV; int n = r2 >> 7, k = r2 & 127;
        v = (n < 128) ? U[(size_t)l*16384 + k*128 + n]
                      : V[(size_t)l*16384 + k*128 + (n-128)];
    } else if (r < OU2) {             // u1T [128,256]
        int r2 = r - OU1; int n = r2 >> 8, k = r2 & 255;
        v = u1[(size_t)l*32768 + k*128 + n];
    } else {                          // u2T [384,128]
        int r2 = r - OU2; int n = r2 >> 7, k = r2 & 127;
        v = u2[(size_t)l*49152 + k*384 + n];
    }
    g_wT[idx] = v;
}

// ---------------- fused message kernel --------------------------------------
__global__ __launch_bounds__(128) void msg_kernel(
    const float* __restrict__ sIn, const float* __restrict__ vIn,
    const float* __restrict__ phi,
    float* __restrict__ sOut, float* __restrict__ vOut,
    const int* __restrict__ idx_j,
    const float* __restrict__ rbw, const float* __restrict__ rbb)
{
    int f = threadIdx.x;
    float wvv[RR], wss[RR], wvs[RR];
    #pragma unroll
    for (int k = 0; k < RR; k++) {
        wvv[k] = rbw[k*F3 + f];
        wss[k] = rbw[k*F3 + FF + f];
        wvs[k] = rbw[k*F3 + 2*FF + f];
    }
    float bvv = rbb[f], bss = rbb[FF+f], bvs = rbb[2*FF+f];

    for (int i = blockIdx.x; i < NN; i += gridDim.x) {
        int p0 = g_rowptr[i], p1 = g_rowptr[i+1];
        float accs = 0.f, av0 = 0.f, av1 = 0.f, av2 = 0.f;
        for (int p = p0; p < p1; p++) {
            int e = g_csr[p];
            int j = idx_j[e];
            float cut = g_cut[e];
            float d0 = g_dir[e*3+0], d1 = g_dir[e*3+1], d2 = g_dir[e*3+2];
            float Wv = bvv*cut, Ws = bss*cut, Wq = bvs*cut;
            const float* rc = &g_rbfc[e*RR];
            #pragma unroll
            for (int k = 0; k < RR; k++) {
                float r = rc[k];
                Wv += r * wvv[k];
                Ws += r * wss[k];
                Wq += r * wvs[k];
            }
            const float* ph = &phi[(size_t)j * F3];
            float pvv = ph[f]        * Wv;
            float pss = ph[FF + f]   * Ws;
            float pvs = ph[2*FF + f] * Wq;
            accs += pss;
            const float* vj = &vIn[(size_t)j * F3];
            av0 += vj[f]        * pvv + pvs * d0;
            av1 += vj[FF + f]   * pvv + pvs * d1;
            av2 += vj[2*FF + f] * pvv + pvs * d2;
        }
        sOut[(size_t)i*FF + f] = sIn[(size_t)i*FF + f] + accs;
        size_t vb = (size_t)i * F3;
        vOut[vb + f]        = vIn[vb + f]        + av0;
        vOut[vb + FF + f]   = vIn[vb + FF + f]   + av1;
        vOut[vb + 2*FF + f] = vIn[vb + 2*FF + f] + av2;
    }
}

// ---------------- x = concat(safe_norm(Vv), sfeat); Vv = g_UVv[:,128:256] ---
__global__ void buildx_kernel(const float* __restrict__ s) {
    int idx = blockIdx.x * blockDim.x + threadIdx.x;
    if (idx >= NN*2*FF) return;
    int n = idx / (2*FF), c = idx % (2*FF);
    if (c < FF) {
        size_t b = (size_t)n * 3 * 256 + 128 + c;
        float v0 = g_UVv[b], v1 = g_UVv[b + 256], v2 = g_UVv[b + 512];
        float sq = v0*v0 + v1*v1 + v2*v2;
        g_x[idx] = (sq > 0.0f) ? sqrtf(sq) : 0.0f;
    } else {
        g_x[idx] = s[(size_t)n*FF + (c - FF)];
    }
}

// ---------------- update block: reads Uv|Vv from g_UVv ----------------------
__global__ void update_kernel(float* __restrict__ s, float* __restrict__ v) {
    int idx = blockIdx.x * blockDim.x + threadIdx.x;
    if (idx >= NN*FF) return;
    int n = idx / FF, f = idx % FF;
    size_t ub = (size_t)n * 3 * 256 + f;
    float u0 = g_UVv[ub],       u1 = g_UVv[ub + 256],       u2 = g_UVv[ub + 512];
    float w0 = g_UVv[ub + 128], w1 = g_UVv[ub + 256 + 128], w2 = g_UVv[ub + 512 + 128];
    float dot = u0*w0 + u1*w1 + u2*w2;
    const float* an = &g_a[(size_t)n * F3];
    float avv = an[f], asv = an[FF + f], ass = an[2*FF + f];
    size_t b = (size_t)n * F3 + f;
    v[b]        += u0 * avv;
    v[b + FF]   += u1 * avv;
    v[b + 2*FF] += u2 * avv;
    s[idx] += ass + asv * dot;
}

__global__ void output_kernel(const float* __restrict__ s, const float* __restrict__ v,
                              float* __restrict__ out) {
    int idx = blockIdx.x * blockDim.x + threadIdx.x;
    if (idx >= NN*FF) return;
    int n = idx / FF, f = idx % FF;
    out[idx] = s[idx];
    size_t ob = (size_t)NN*FF + (size_t)idx * 3;
    size_t vb = (size_t)n * F3 + f;
    out[ob + 0] = v[vb];
    out[ob + 1] = v[vb + FF];
    out[ob + 2] = v[vb + 2*FF];
}

// ---------------- host orchestration ----------------------------------------
static inline void launch_gemm(const float* A, const float* BT, const float* bias,
                               float* C, int M, int K, int N, int act) {
    dim3 grid(N / GBN, (M + GBM - 1) / GBM);
    gemm_bf16_kernel<<<grid, 256>>>(A, BT, bias, C, M, K, N, act);
}

extern "C" void kernel_launch(void* const* d_in, const int* in_sizes, int n_in,
                              void* d_out, int out_size) {
    const int*   z      = (const int*)  d_in[0];
    const float* pos    = (const float*)d_in[1];
    const int*   idx_i  = (const int*)  d_in[2];
    const int*   idx_j  = (const int*)  d_in[3];
    const float* emb    = (const float*)d_in[4];
    const float* msg_w1 = (const float*)d_in[5];
    const float* msg_b1 = (const float*)d_in[6];
    const float* msg_w2 = (const float*)d_in[7];
    const float* msg_b2 = (const float*)d_in[8];
    const float* rbf_w  = (const float*)d_in[9];
    const float* rbf_b  = (const float*)d_in[10];
    const float* upd_U  = (const float*)d_in[11];
    const float* upd_V  = (const float*)d_in[12];
    const float* upd_w1 = (const float*)d_in[13];
    const float* upd_b1 = (const float*)d_in[14];
    const float* upd_w2 = (const float*)d_in[15];
    const float* upd_b2 = (const float*)d_in[16];
    float* out = (float*)d_out;

    float *sA, *sB, *vA, *vB, *phi, *hid, *wT, *UVv, *aa, *xx;
    cudaGetSymbolAddress((void**)&sA,  g_sA);
    cudaGetSymbolAddress((void**)&sB,  g_sB);
    cudaGetSymbolAddress((void**)&vA,  g_vA);
    cudaGetSymbolAddress((void**)&vB,  g_vB);
    cudaGetSymbolAddress((void**)&phi, g_phi);
    cudaGetSymbolAddress((void**)&hid, g_hid);
    cudaGetSymbolAddress((void**)&wT,  g_wT);
    cudaGetSymbolAddress((void**)&UVv, g_UVv);
    cudaGetSymbolAddress((void**)&aa,  g_a);
    cudaGetSymbolAddress((void**)&xx,  g_x);

    // ---- setup (replayed each graph iteration; deterministic) ----
    pack_w_kernel<<<(LL*PS + 255)/256, 256>>>(msg_w1, msg_w2, upd_U, upd_V, upd_w1, upd_w2);
    init_kernel<<<(NN*FF + 255)/256, 256>>>(z, emb);
    zero_counts_kernel<<<(NN + 255)/256, 256>>>();

    float* sCur = sA; float* sNxt = sB;
    float* vCur = vA; float* vNxt = vB;

    for (int l = 0; l < 3; l++) {
        const float* lw = wT + (size_t)l * PS;
        // hid = silu(s @ w1 + b1)
        launch_gemm(sCur, lw + OW1, msg_b1 + (size_t)l*FF, hid, NN, FF, 128, 1);
        if (l == 0) {
            edge_pre_kernel<<<(EE + 255)/256, 256>>>(pos, idx_i, idx_j);
            scan_kernel<<<1, 1024>>>();
            scatter_kernel<<<(EE + 255)/256, 256>>>(idx_i);
        }
        // phi = hid @ w2 + b2
        launch_gemm(hid, lw + OW2, msg_b2 + (size_t)l*F3, phi, NN, FF, 384, 0);
        // message pass
        msg_kernel<<<2000, 128>>>(sCur, vCur, phi, sNxt, vNxt, idx_j,
                                  rbf_w + (size_t)l*RR*F3, rbf_b + (size_t)l*F3);
        // [Uv | Vv] = vNxt[3N,F] @ UVw[F,2F]
        launch_gemm(vNxt, lw + OUV, nullptr, UVv, 3*NN, FF, 256, 0);
        // x = concat(||Vv||, s)
        buildx_kernel<<<(NN*2*FF + 255)/256, 256>>>(sNxt);
        // hid = silu(x @ uw1 + ub1);  a = hid @ uw2 + ub2
        launch_gemm(xx, lw + OU1, upd_b1 + (size_t)l*FF, hid, NN, 2*FF, 128, 1);
        launch_gemm(hid, lw + OU2, upd_b2 + (size_t)l*F3, aa, NN, FF, 384, 0);
        // in-place update
        update_kernel<<<(NN*FF + 255)/256, 256>>>(sNxt, vNxt);

        float* t;
        t = sCur; sCur = sNxt; sNxt = t;
        t = vCur; vCur = vNxt; vNxt = t;
    }

    output_kernel<<<(NN*FF + 255)/256, 256>>>(sCur, vCur, out);
}